// round 2
// baseline (speedup 1.0000x reference)
#include <cuda_runtime.h>
#include <cuda_bf16.h>

// Problem constants
#define BATCH 32
#define TT    1024          // time steps
#define DD    256           // code dim
#define KK    1024          // num codes
#define NN    (BATCH*TT)    // 32768 rows
#define DT    (DD*TT)       // 262144, per-batch latent stride

#define OUT_Q_OFF    0
#define OUT_LOSS_OFF 8388608
#define OUT_IDX_OFF  8388609

// -------- device scratch (no allocations allowed) --------
__device__ float               g_Wt[DD * KK];      // [d][k]
__device__ float               g_wnorm[KK];
__device__ float               g_xnorm[NN];
__device__ unsigned long long  g_best[NN];
__device__ double              g_loss;

// ---------------------------------------------------------
// init: best = max, loss = 0
__global__ void vq_init_kernel() {
    int i = blockIdx.x * blockDim.x + threadIdx.x;
    if (i < NN) g_best[i] = 0xFFFFFFFFFFFFFFFFULL;
    if (i == 0) g_loss = 0.0;
}

// ---------------------------------------------------------
// prep: transpose codebook into Wt[d][k], compute wnorm[k]
__global__ void vq_prep_w_kernel(const float* __restrict__ cb) {
    __shared__ double sred[256];
    int k = blockIdx.x;        // 0..1023
    int d = threadIdx.x;       // 0..255
    float w = cb[k * DD + d];
    g_Wt[d * KK + k] = w;
    sred[d] = (double)w * (double)w;
    __syncthreads();
    for (int s = 128; s > 0; s >>= 1) {
        if (d < s) sred[d] += sred[d + s];
        __syncthreads();
    }
    if (d == 0) g_wnorm[k] = (float)sred[0];
}

// ---------------------------------------------------------
// xnorm[n] = sum_d latents[b,d,t]^2  (fp64 accum -> f32)
__global__ void vq_xnorm_kernel(const float* __restrict__ lat) {
    int n = blockIdx.x * blockDim.x + threadIdx.x;
    if (n >= NN) return;
    int b = n >> 10;
    int t = n & 1023;
    const float* p = lat + (size_t)b * DT + t;
    double s = 0.0;
    #pragma unroll 8
    for (int d = 0; d < DD; d++) {
        float v = p[(size_t)d * TT];
        s += (double)v * (double)v;
    }
    g_xnorm[n] = (float)s;
}

// ---------------------------------------------------------
// main: distance GEMM + argmin
// CTA: 128 rows x 512 codes, 256 threads, tc = tid&15 (codes), tr = tid>>4 (rows)
// smem: xs[256][128] (x-tile, persistent), ws[64][256] (code tile, duplicated pairs),
//       xnorm_s[128]
#define FFMA2(acc, a, b) asm("fma.rn.f32x2 %0, %1, %2, %0;" : "+l"(acc) : "l"(a), "l"(b))

__global__ void __launch_bounds__(256, 1)
vq_main_kernel(const float* __restrict__ lat) {
    extern __shared__ float sm[];
    float* xs      = sm;                   // 32768 floats (128 KB)
    float* ws      = sm + 32768;           // 16384 floats (64 KB), duplicated pairs
    float* xnorm_s = sm + 32768 + 16384;   // 128 floats

    const int tid = threadIdx.x;
    const int tc  = tid & 15;
    const int tr  = tid >> 4;

    const int mtile = blockIdx.x;              // 0..255
    const int b     = mtile >> 3;
    const int t0    = (mtile & 7) << 7;        // 0..896
    const int kbase = blockIdx.y << 9;         // 0 or 512
    const int n0    = mtile << 7;              // global row base

    // load x tile: xs[d][m] = lat[b, d, t0+m]
    {
        const float4* latb = (const float4*)(lat + (size_t)b * DT + t0);
        float4* xs4 = (float4*)xs;
        #pragma unroll
        for (int i = tid; i < 8192; i += 256) {
            int d  = i >> 5;
            int m4 = i & 31;
            xs4[d * 32 + m4] = latb[d * 256 + m4];
        }
        if (tid < 128) xnorm_s[tid] = g_xnorm[n0 + tid];
    }

    unsigned long long best[8];
    #pragma unroll
    for (int i = 0; i < 8; i++) best[i] = 0xFFFFFFFFFFFFFFFFULL;

    for (int kc = 0; kc < 4; kc++) {
        const int k0 = kbase + (kc << 7);      // 128 codes this chunk
        unsigned long long acc[4][8];
        #pragma unroll
        for (int i = 0; i < 4; i++)
            #pragma unroll
            for (int j = 0; j < 8; j++) acc[i][j] = 0ULL;

        for (int ds = 0; ds < 4; ds++) {
            __syncthreads();   // protect ws overwrite (also covers initial xs fill)
            // fill ws duplicated: ws[dl][2k+{0,1}] = Wt[ds*64+dl][k0+k]
            {
                const float4* wt4 = (const float4*)g_Wt;
                #pragma unroll
                for (int i = tid; i < 2048; i += 256) {
                    int dl = i >> 5;
                    int c4 = i & 31;
                    float4 w = wt4[(ds * 64 + dl) * 256 + (k0 >> 2) + c4];
                    float4* dst = (float4*)(ws + dl * 256 + c4 * 8);
                    dst[0] = make_float4(w.x, w.x, w.y, w.y);
                    dst[1] = make_float4(w.z, w.z, w.w, w.w);
                }
            }
            __syncthreads();

            #pragma unroll 4
            for (int dl = 0; dl < 64; dl++) {
                const unsigned long long* xp =
                    (const unsigned long long*)(xs + (ds * 64 + dl) * 128);
                const unsigned long long* wp =
                    (const unsigned long long*)(ws + dl * 256);
                unsigned long long x0 = xp[tr];
                unsigned long long x1 = xp[tr + 16];
                unsigned long long x2 = xp[tr + 32];
                unsigned long long x3 = xp[tr + 48];
                unsigned long long w[8];
                #pragma unroll
                for (int j = 0; j < 8; j++) w[j] = wp[tc + 16 * j];
                #pragma unroll
                for (int j = 0; j < 8; j++) {
                    FFMA2(acc[0][j], x0, w[j]);
                    FFMA2(acc[1][j], x1, w[j]);
                    FFMA2(acc[2][j], x2, w[j]);
                    FFMA2(acc[3][j], x3, w[j]);
                }
            }
        }

        // epilogue: dist + local argmin (replicates fl(fl(xnorm-2*dot)+wnorm))
        #pragma unroll
        for (int i = 0; i < 4; i++) {
            int m0 = 2 * tr + 32 * i;
            float xn0 = xnorm_s[m0];
            float xn1 = xnorm_s[m0 + 1];
            #pragma unroll
            for (int j = 0; j < 8; j++) {
                int k = k0 + tc + 16 * j;
                float wn = g_wnorm[k];
                float dot0 = __uint_as_float((unsigned)(acc[i][j] & 0xFFFFFFFFULL));
                float dot1 = __uint_as_float((unsigned)(acc[i][j] >> 32));
                float dist0 = __fadd_rn(__fmaf_rn(-2.0f, dot0, xn0), wn);
                float dist1 = __fadd_rn(__fmaf_rn(-2.0f, dot1, xn1), wn);
                unsigned long long p0 =
                    ((unsigned long long)__float_as_uint(dist0) << 32) | (unsigned)k;
                unsigned long long p1 =
                    ((unsigned long long)__float_as_uint(dist1) << 32) | (unsigned)k;
                if (p0 < best[2 * i])     best[2 * i]     = p0;
                if (p1 < best[2 * i + 1]) best[2 * i + 1] = p1;
            }
        }
    }

    // reduce across the 16 code-lanes (tc) then atomicMin into global
    #pragma unroll
    for (int r = 0; r < 8; r++) {
        unsigned long long v = best[r];
        #pragma unroll
        for (int ofs = 1; ofs < 16; ofs <<= 1) {
            unsigned long long o = __shfl_xor_sync(0xFFFFFFFFu, v, ofs);
            if (o < v) v = o;
        }
        best[r] = v;
    }
    if (tc == 0) {
        #pragma unroll
        for (int i = 0; i < 4; i++) {
            int m0 = 2 * tr + 32 * i;
            atomicMin(&g_best[n0 + m0],     best[2 * i]);
            atomicMin(&g_best[n0 + m0 + 1], best[2 * i + 1]);
        }
    }
}

// ---------------------------------------------------------
// quantize + straight-through + loss partial + index output
// CTA: one (b, 64-t chunk); 256 threads.
__global__ void __launch_bounds__(256)
vq_quant_kernel(const float* __restrict__ lat, const float* __restrict__ cb,
                float* __restrict__ out) {
    extern __shared__ float qsm[];
    float*        q_s   = qsm;                      // [64][256]
    unsigned*     idx_s = (unsigned*)(qsm + 64 * 256);   // [64]
    float*        red   = (float*)(idx_s + 64);     // [256]

    const int tid = threadIdx.x;
    const int cid = blockIdx.x;     // 0..511
    const int b   = cid >> 4;
    const int t0  = (cid & 15) << 6;

    if (tid < 64) {
        int n = b * TT + t0 + tid;
        unsigned k = (unsigned)(g_best[n] & 0xFFFFFFFFULL);
        idx_s[tid] = k;
        out[OUT_IDX_OFF + n] = (float)k;
    }
    __syncthreads();

    // gather 64 codebook rows into smem
    {
        const float4* cb4 = (const float4*)cb;
        float4* q4 = (float4*)q_s;
        #pragma unroll
        for (int i = tid; i < 4096; i += 256) {
            int r = i >> 6;
            int c = i & 63;
            q4[r * 64 + c] = cb4[idx_s[r] * 64 + c];
        }
    }
    __syncthreads();

    // write quantized_st (coalesced along t) + accumulate loss
    const int d = tid;
    const size_t base = ((size_t)b * DD + d) * TT + t0;
    float lsum = 0.0f;
    #pragma unroll 4
    for (int tt = 0; tt < 64; tt += 4) {
        float4 x4 = *(const float4*)(lat + base + tt);
        float q0 = q_s[(tt + 0) * 256 + d];
        float q1 = q_s[(tt + 1) * 256 + d];
        float q2 = q_s[(tt + 2) * 256 + d];
        float q3 = q_s[(tt + 3) * 256 + d];
        float d0 = __fsub_rn(q0, x4.x);
        float d1 = __fsub_rn(q1, x4.y);
        float d2 = __fsub_rn(q2, x4.z);
        float d3 = __fsub_rn(q3, x4.w);
        float4 st;
        st.x = __fadd_rn(x4.x, d0);
        st.y = __fadd_rn(x4.y, d1);
        st.z = __fadd_rn(x4.z, d2);
        st.w = __fadd_rn(x4.w, d3);
        *(float4*)(out + OUT_Q_OFF + base + tt) = st;
        lsum = __fmaf_rn(d0, d0, lsum);
        lsum = __fmaf_rn(d1, d1, lsum);
        lsum = __fmaf_rn(d2, d2, lsum);
        lsum = __fmaf_rn(d3, d3, lsum);
    }

    red[tid] = lsum;
    __syncthreads();
    for (int s = 128; s > 0; s >>= 1) {
        if (tid < s) red[tid] += red[tid + s];
        __syncthreads();
    }
    if (tid == 0) atomicAdd(&g_loss, (double)red[0]);
}

// ---------------------------------------------------------
__global__ void vq_finalize_kernel(float* __restrict__ out) {
    if (threadIdx.x == 0 && blockIdx.x == 0) {
        double mean = g_loss / (double)(NN * DD);
        out[OUT_LOSS_OFF] = (float)(mean * 1.25);
    }
}

// ---------------------------------------------------------
extern "C" void kernel_launch(void* const* d_in, const int* in_sizes, int n_in,
                              void* d_out, int out_size) {
    const float* lat = (const float*)d_in[0];   // [32, 256, 1024]
    const float* cb  = (const float*)d_in[1];   // [1024, 256]
    float* out = (float*)d_out;

    // dynamic smem sizes
    const int MAIN_SMEM  = (32768 + 16384 + 128) * 4;   // 197120 B
    const int QUANT_SMEM = (64 * 256 + 64 + 256) * 4 + 256;

    cudaFuncSetAttribute(vq_main_kernel,
                         cudaFuncAttributeMaxDynamicSharedMemorySize, MAIN_SMEM);
    cudaFuncSetAttribute(vq_quant_kernel,
                         cudaFuncAttributeMaxDynamicSharedMemorySize, QUANT_SMEM);

    vq_init_kernel<<<NN / 256, 256>>>();
    vq_prep_w_kernel<<<KK, 256>>>(cb);
    vq_xnorm_kernel<<<NN / 256, 256>>>(lat);

    dim3 grid(256, 2);
    vq_main_kernel<<<grid, 256, MAIN_SMEM>>>(lat);

    vq_quant_kernel<<<512, 256, QUANT_SMEM>>>(lat, cb, out);
    vq_finalize_kernel<<<1, 1>>>(out);
}

// round 3
// speedup vs baseline: 1.3250x; 1.3250x over previous
#include <cuda_runtime.h>
#include <cuda_bf16.h>
#include <cstdint>

// Problem constants
#define BATCH 32
#define TT    1024          // time steps
#define DD    256           // code dim
#define KK    1024          // num codes
#define NN    (BATCH*TT)    // 32768 rows
#define DT    (DD*TT)       // per-batch latent stride

#define OUT_Q_OFF    0
#define OUT_LOSS_OFF 8388608
#define OUT_IDX_OFF  8388609

typedef unsigned long long ull;

// -------- device scratch (no allocations allowed) --------
__device__ float g_Wdup[DD * 2 * KK];   // [d][2k] duplicated pairs (w,w)
__device__ float g_wnorm[KK];
__device__ float g_xnorm[NN];
__device__ ull   g_best[NN];
__device__ double g_loss;

// ---------------------------------------------------------
__device__ __forceinline__ uint32_t smem_u32(const void* p) {
    uint32_t a;
    asm("{ .reg .u64 t; cvta.to.shared.u64 t, %1; cvt.u32.u64 %0, t; }"
        : "=r"(a) : "l"(p));
    return a;
}
__device__ __forceinline__ void cp_async16(uint32_t s, const void* g) {
    asm volatile("cp.async.cg.shared.global [%0], [%1], 16;" :: "r"(s), "l"(g));
}
#define CP_COMMIT() asm volatile("cp.async.commit_group;")
#define CP_WAIT(N)  asm volatile("cp.async.wait_group %0;" :: "n"(N))

#define FFMA2(acc, a, b) asm("fma.rn.f32x2 %0, %1, %2, %0;" : "+l"(acc) : "l"(a), "l"(b))

// ---------------------------------------------------------
__global__ void vq_init_kernel() {
    int i = blockIdx.x * blockDim.x + threadIdx.x;
    if (i < NN) g_best[i] = 0xFFFFFFFFFFFFFFFFULL;
    if (i == 0) g_loss = 0.0;
}

// prep: duplicate-transpose codebook into Wdup[d][2k], compute wnorm[k]
__global__ void vq_prep_w_kernel(const float* __restrict__ cb) {
    __shared__ double sred[256];
    int k = blockIdx.x;        // 0..1023
    int d = threadIdx.x;       // 0..255
    float w = cb[k * DD + d];
    float2* dst = (float2*)(g_Wdup + (size_t)d * 2 * KK) + k;
    *dst = make_float2(w, w);
    sred[d] = (double)w * (double)w;
    __syncthreads();
    for (int s = 128; s > 0; s >>= 1) {
        if (d < s) sred[d] += sred[d + s];
        __syncthreads();
    }
    if (d == 0) g_wnorm[k] = (float)sred[0];
}

// xnorm[n] = sum_d latents[b,d,t]^2 (fp64 accum -> f32)
__global__ void vq_xnorm_kernel(const float* __restrict__ lat) {
    int n = blockIdx.x * blockDim.x + threadIdx.x;
    if (n >= NN) return;
    int b = n >> 10;
    int t = n & 1023;
    const float* p = lat + (size_t)b * DT + t;
    double s = 0.0;
    #pragma unroll 8
    for (int d = 0; d < DD; d++) {
        float v = p[(size_t)d * TT];
        s += (double)v * (double)v;
    }
    g_xnorm[n] = (float)s;
}

// ---------------------------------------------------------
// main: 128 rows x 256 codes per CTA, 512 threads (two 128-code halves),
// per-thread 8 rows x 8 codes of f32x2 accumulators.
// smem: xs[256][128] persistent x tile, ws[2][16][512] double-buffered dup-W
//       chunks streamed via cp.async, + xnorm/wnorm caches.
__global__ void __launch_bounds__(512, 1)
vq_main_kernel(const float* __restrict__ lat) {
    extern __shared__ float sm[];
    float* xs   = sm;                        // 32768 floats (128 KB)
    float* ws   = sm + 32768;                // 2*8192 floats (64 KB)
    float* xn_s = sm + 32768 + 16384;        // 128
    float* wn_s = xn_s + 128;                // 256

    const int tid = threadIdx.x;
    const int kk2 = tid >> 8;                // code half 0/1
    const int tc  = tid & 15;                // code lane
    const int tr  = (tid >> 4) & 15;         // row lane

    const int mtile = blockIdx.x;            // 0..255
    const int b     = mtile >> 3;
    const int t0    = (mtile & 7) << 7;
    const int kbase = blockIdx.y << 8;       // 0,256,512,768
    const int n0    = mtile << 7;

    const uint32_t xs_a = smem_u32(xs);
    const uint32_t ws_a = smem_u32(ws);

    // ---- prologue: async-load x tile, first W chunk, norm caches ----
    {
        const float* latb = lat + (size_t)b * DT + t0;
        #pragma unroll 4
        for (int u = tid; u < 8192; u += 512) {
            int d = u >> 5, m4 = u & 31;
            cp_async16(xs_a + (uint32_t)(d * 128 + m4 * 4) * 4,
                       latb + (size_t)d * TT + m4 * 4);
        }
        // ws chunk 0 -> buf 0
        const float* src = g_Wdup + (size_t)kbase * 2;
        #pragma unroll
        for (int u = tid; u < 2048; u += 512) {
            int r = u >> 7, c = u & 127;
            cp_async16(ws_a + (uint32_t)(r * 512 + c * 4) * 4,
                       src + (size_t)r * 2048 + c * 4);
        }
        if (tid < 32)
            cp_async16(smem_u32(xn_s) + tid * 16, g_xnorm + n0 + tid * 4);
        else if (tid < 96)
            cp_async16(smem_u32(wn_s) + (tid - 32) * 16,
                       g_wnorm + kbase + (tid - 32) * 4);
        CP_COMMIT();
    }

    ull acc[4][8];
    #pragma unroll
    for (int i = 0; i < 4; i++)
        #pragma unroll
        for (int j = 0; j < 8; j++) acc[i][j] = 0ULL;

    // ---- main loop: 16 chunks of 16 d-rows, double buffered ----
    for (int ch = 0; ch < 16; ch++) {
        if (ch < 15) {
            const float* src = g_Wdup + (size_t)(ch + 1) * 16 * 2048 + kbase * 2;
            uint32_t dst = ws_a + (uint32_t)(((ch + 1) & 1) * 8192) * 4;
            #pragma unroll
            for (int u = tid; u < 2048; u += 512) {
                int r = u >> 7, c = u & 127;
                cp_async16(dst + (uint32_t)(r * 512 + c * 4) * 4,
                           src + (size_t)r * 2048 + c * 4);
            }
            CP_COMMIT();
            CP_WAIT(1);
        } else {
            CP_WAIT(0);
        }
        __syncthreads();

        const float* wb = ws + (ch & 1) * 8192;
        #pragma unroll 4
        for (int dl = 0; dl < 16; dl++) {
            const ull* xp = (const ull*)(xs + ((ch << 4) + dl) * 128);
            const ulonglong2* wp =
                (const ulonglong2*)(wb + dl * 512) + kk2 * 64;
            ull x0 = xp[tr];
            ull x1 = xp[tr + 16];
            ull x2 = xp[tr + 32];
            ull x3 = xp[tr + 48];
            ulonglong2 w0 = wp[tc];
            ulonglong2 w1 = wp[tc + 16];
            ulonglong2 w2 = wp[tc + 32];
            ulonglong2 w3 = wp[tc + 48];
            FFMA2(acc[0][0], x0, w0.x); FFMA2(acc[1][0], x1, w0.x);
            FFMA2(acc[2][0], x2, w0.x); FFMA2(acc[3][0], x3, w0.x);
            FFMA2(acc[0][1], x0, w0.y); FFMA2(acc[1][1], x1, w0.y);
            FFMA2(acc[2][1], x2, w0.y); FFMA2(acc[3][1], x3, w0.y);
            FFMA2(acc[0][2], x0, w1.x); FFMA2(acc[1][2], x1, w1.x);
            FFMA2(acc[2][2], x2, w1.x); FFMA2(acc[3][2], x3, w1.x);
            FFMA2(acc[0][3], x0, w1.y); FFMA2(acc[1][3], x1, w1.y);
            FFMA2(acc[2][3], x2, w1.y); FFMA2(acc[3][3], x3, w1.y);
            FFMA2(acc[0][4], x0, w2.x); FFMA2(acc[1][4], x1, w2.x);
            FFMA2(acc[2][4], x2, w2.x); FFMA2(acc[3][4], x3, w2.x);
            FFMA2(acc[0][5], x0, w2.y); FFMA2(acc[1][5], x1, w2.y);
            FFMA2(acc[2][5], x2, w2.y); FFMA2(acc[3][5], x3, w2.y);
            FFMA2(acc[0][6], x0, w3.x); FFMA2(acc[1][6], x1, w3.x);
            FFMA2(acc[2][6], x2, w3.x); FFMA2(acc[3][6], x3, w3.x);
            FFMA2(acc[0][7], x0, w3.y); FFMA2(acc[1][7], x1, w3.y);
            FFMA2(acc[2][7], x2, w3.y); FFMA2(acc[3][7], x3, w3.y);
        }
        __syncthreads();
    }

    // ---- epilogue: dist = fl(fl(xnorm - 2*dot) + wnorm), packed argmin ----
    ull best[8];
    #pragma unroll
    for (int r = 0; r < 8; r++) best[r] = 0xFFFFFFFFFFFFFFFFULL;

    #pragma unroll
    for (int i = 0; i < 4; i++) {
        int m0 = 2 * tr + 32 * i;
        float xn0 = xn_s[m0];
        float xn1 = xn_s[m0 + 1];
        #pragma unroll
        for (int j2 = 0; j2 < 4; j2++) {
            #pragma unroll
            for (int s = 0; s < 2; s++) {
                int j = 2 * j2 + s;
                int klocal = kk2 * 128 + 2 * (tc + 16 * j2) + s;
                float wn = wn_s[klocal];
                unsigned k = (unsigned)(kbase + klocal);
                float dot0 = __uint_as_float((unsigned)(acc[i][j] & 0xFFFFFFFFULL));
                float dot1 = __uint_as_float((unsigned)(acc[i][j] >> 32));
                float dist0 = __fadd_rn(__fmaf_rn(-2.0f, dot0, xn0), wn);
                float dist1 = __fadd_rn(__fmaf_rn(-2.0f, dot1, xn1), wn);
                ull p0 = ((ull)__float_as_uint(dist0) << 32) | k;
                ull p1 = ((ull)__float_as_uint(dist1) << 32) | k;
                if (p0 < best[2 * i])     best[2 * i]     = p0;
                if (p1 < best[2 * i + 1]) best[2 * i + 1] = p1;
            }
        }
    }

    // reduce across the 16 code-lanes (lane bits 0..3), then global atomicMin
    #pragma unroll
    for (int r = 0; r < 8; r++) {
        ull v = best[r];
        #pragma unroll
        for (int ofs = 1; ofs < 16; ofs <<= 1) {
            ull o = __shfl_xor_sync(0xFFFFFFFFu, v, ofs);
            if (o < v) v = o;
        }
        best[r] = v;
    }
    if (tc == 0) {
        #pragma unroll
        for (int i = 0; i < 4; i++) {
            int m0 = 2 * tr + 32 * i;
            atomicMin(&g_best[n0 + m0],     best[2 * i]);
            atomicMin(&g_best[n0 + m0 + 1], best[2 * i + 1]);
        }
    }
}

// ---------------------------------------------------------
// quantize + straight-through + loss partial + index output
__global__ void __launch_bounds__(256)
vq_quant_kernel(const float* __restrict__ lat, const float* __restrict__ cb,
                float* __restrict__ out) {
    extern __shared__ float qsm[];
    float*    q_s   = qsm;                           // [64][256]
    unsigned* idx_s = (unsigned*)(qsm + 64 * 256);   // [64]
    float*    red   = (float*)(idx_s + 64);          // [256]

    const int tid = threadIdx.x;
    const int cid = blockIdx.x;     // 0..511
    const int b   = cid >> 4;
    const int t0  = (cid & 15) << 6;

    if (tid < 64) {
        int n = b * TT + t0 + tid;
        unsigned k = (unsigned)(g_best[n] & 0xFFFFFFFFULL);
        idx_s[tid] = k;
        out[OUT_IDX_OFF + n] = (float)k;
    }
    __syncthreads();

    {
        const float4* cb4 = (const float4*)cb;
        float4* q4 = (float4*)q_s;
        #pragma unroll
        for (int i = tid; i < 4096; i += 256) {
            int r = i >> 6, c = i & 63;
            q4[r * 64 + c] = cb4[idx_s[r] * 64 + c];
        }
    }
    __syncthreads();

    const int d = tid;
    const size_t base = ((size_t)b * DD + d) * TT + t0;
    float lsum = 0.0f;
    #pragma unroll 4
    for (int tt = 0; tt < 64; tt += 4) {
        float4 x4 = *(const float4*)(lat + base + tt);
        float q0 = q_s[(tt + 0) * 256 + d];
        float q1 = q_s[(tt + 1) * 256 + d];
        float q2 = q_s[(tt + 2) * 256 + d];
        float q3 = q_s[(tt + 3) * 256 + d];
        float d0 = __fsub_rn(q0, x4.x);
        float d1 = __fsub_rn(q1, x4.y);
        float d2 = __fsub_rn(q2, x4.z);
        float d3 = __fsub_rn(q3, x4.w);
        float4 st;
        st.x = __fadd_rn(x4.x, d0);
        st.y = __fadd_rn(x4.y, d1);
        st.z = __fadd_rn(x4.z, d2);
        st.w = __fadd_rn(x4.w, d3);
        *(float4*)(out + OUT_Q_OFF + base + tt) = st;
        lsum = __fmaf_rn(d0, d0, lsum);
        lsum = __fmaf_rn(d1, d1, lsum);
        lsum = __fmaf_rn(d2, d2, lsum);
        lsum = __fmaf_rn(d3, d3, lsum);
    }

    red[tid] = lsum;
    __syncthreads();
    for (int s = 128; s > 0; s >>= 1) {
        if (tid < s) red[tid] += red[tid + s];
        __syncthreads();
    }
    if (tid == 0) atomicAdd(&g_loss, (double)red[0]);
}

// ---------------------------------------------------------
__global__ void vq_finalize_kernel(float* __restrict__ out) {
    if (threadIdx.x == 0 && blockIdx.x == 0) {
        double mean = g_loss / (double)((size_t)NN * DD);
        out[OUT_LOSS_OFF] = (float)(mean * 1.25);
    }
}

// ---------------------------------------------------------
extern "C" void kernel_launch(void* const* d_in, const int* in_sizes, int n_in,
                              void* d_out, int out_size) {
    const float* lat = (const float*)d_in[0];   // [32, 256, 1024]
    const float* cb  = (const float*)d_in[1];   // [1024, 256]
    float* out = (float*)d_out;

    const int MAIN_SMEM  = (32768 + 16384 + 128 + 256) * 4;   // 198144 B
    const int QUANT_SMEM = (64 * 256 + 64 + 256) * 4 + 256;

    cudaFuncSetAttribute(vq_main_kernel,
                         cudaFuncAttributeMaxDynamicSharedMemorySize, MAIN_SMEM);
    cudaFuncSetAttribute(vq_quant_kernel,
                         cudaFuncAttributeMaxDynamicSharedMemorySize, QUANT_SMEM);

    vq_init_kernel<<<NN / 256, 256>>>();
    vq_prep_w_kernel<<<KK, 256>>>(cb);
    vq_xnorm_kernel<<<NN / 256, 256>>>(lat);

    dim3 grid(256, 4);
    vq_main_kernel<<<grid, 512, MAIN_SMEM>>>(lat);

    vq_quant_kernel<<<512, 256, QUANT_SMEM>>>(lat, cb, out);
    vq_finalize_kernel<<<1, 1>>>(out);
}

// round 4
// speedup vs baseline: 1.4712x; 1.1103x over previous
#include <cuda_runtime.h>
#include <cuda_bf16.h>
#include <cstdint>

// Problem constants
#define BATCH 32
#define TT    1024          // time steps
#define DD    256           // code dim
#define KK    1024          // num codes
#define NN    (BATCH*TT)    // 32768 rows
#define DT    (DD*TT)       // per-batch latent stride

#define OUT_Q_OFF    0
#define OUT_LOSS_OFF 8388608
#define OUT_IDX_OFF  8388609

typedef unsigned long long ull;

// -------- device scratch (no allocations allowed) --------
__device__ float  g_Wt[DD * KK];     // [d][k] transposed codebook
__device__ float  g_wnorm[KK];
__device__ float  g_xnorm[NN];
__device__ ull    g_best[NN];
__device__ double g_loss;

// ---------------------------------------------------------
__device__ __forceinline__ uint32_t smem_u32(const void* p) {
    uint32_t a;
    asm("{ .reg .u64 t; cvta.to.shared.u64 t, %1; cvt.u32.u64 %0, t; }"
        : "=r"(a) : "l"(p));
    return a;
}
__device__ __forceinline__ void cp_async16(uint32_t s, const void* g) {
    asm volatile("cp.async.cg.shared.global [%0], [%1], 16;" :: "r"(s), "l"(g));
}
#define CP_COMMIT() asm volatile("cp.async.commit_group;")
#define CP_WAIT(N)  asm volatile("cp.async.wait_group %0;" :: "n"(N))

#define FFMA2(acc, a, b) asm("fma.rn.f32x2 %0, %1, %2, %0;" : "+l"(acc) : "l"(a), "l"(b))
#define PACK2(dst, w)    asm("mov.b64 %0, {%1, %1};" : "=l"(dst) : "r"(w))

// ---------------------------------------------------------
// prep: transpose codebook into Wt[d][k], compute wnorm[k]; zero loss
__global__ void vq_prep_w_kernel(const float* __restrict__ cb) {
    __shared__ double sred[256];
    int k = blockIdx.x;        // 0..1023
    int d = threadIdx.x;       // 0..255
    float w = cb[k * DD + d];
    g_Wt[d * KK + k] = w;
    sred[d] = (double)w * (double)w;
    __syncthreads();
    for (int s = 128; s > 0; s >>= 1) {
        if (d < s) sred[d] += sred[d + s];
        __syncthreads();
    }
    if (d == 0) {
        g_wnorm[k] = (float)sred[0];
        if (k == 0) g_loss = 0.0;
    }
}

// xnorm[n] = sum_d latents[b,d,t]^2 (fp64 accum -> f32); also init g_best
__global__ void vq_xnorm_kernel(const float* __restrict__ lat) {
    int n = blockIdx.x * blockDim.x + threadIdx.x;
    if (n >= NN) return;
    g_best[n] = 0xFFFFFFFFFFFFFFFFULL;
    int b = n >> 10;
    int t = n & 1023;
    const float* p = lat + (size_t)b * DT + t;
    double s = 0.0;
    #pragma unroll 8
    for (int d = 0; d < DD; d++) {
        float v = p[(size_t)d * TT];
        s += (double)v * (double)v;
    }
    g_xnorm[n] = (float)s;
}

// ---------------------------------------------------------
// main: 128 rows x 256 codes per CTA, 512 threads.
// thread (tc, tr, kk2): rows 8*tr..8*tr+7 (4 ull pairs), 8 codes
//   codes = kk2*128 + {tc*4+0..3, 64+tc*4+0..3}
// smem: xs[256][128] persistent x tile, ws[3][16][256] triple-buffered W
//       chunks (non-duplicated) streamed via cp.async + norm caches.
__global__ void __launch_bounds__(512, 1)
vq_main_kernel(const float* __restrict__ lat) {
    extern __shared__ float sm[];
    float* xs   = sm;                        // 32768 floats (128 KB)
    float* ws   = sm + 32768;                // 3*4096 floats (48 KB)
    float* xn_s = sm + 32768 + 12288;        // 128
    float* wn_s = xn_s + 128;                // 256

    const int tid = threadIdx.x;
    const int tc  = tid & 15;                // code lane
    const int tr  = (tid >> 4) & 15;         // row group
    const int kk2 = tid >> 8;                // code half 0/1

    const int mtile = blockIdx.x;            // 0..255
    const int b     = mtile >> 3;
    const int t0    = (mtile & 7) << 7;
    const int kbase = blockIdx.y << 8;       // 0,256,512,768
    const int n0    = mtile << 7;

    const uint32_t xs_a = smem_u32(xs);
    const uint32_t ws_a = smem_u32(ws);

    // ---- prologue ----
    // group 0: x tile + W chunk 0 + norm caches; group 1: W chunk 1
    {
        const float* latb = lat + (size_t)b * DT + t0;
        #pragma unroll 4
        for (int u = tid; u < 8192; u += 512) {
            int d = u >> 5, m4 = u & 31;
            cp_async16(xs_a + (uint32_t)(d * 128 + m4 * 4) * 4,
                       latb + (size_t)d * TT + m4 * 4);
        }
        // W chunk 0 -> buf 0 : ws[r][c] = Wt[r][kbase + c], r=0..15, c=0..255
        #pragma unroll
        for (int u = tid; u < 1024; u += 512) {
            int r = u >> 6, c4 = u & 63;
            cp_async16(ws_a + (uint32_t)(r * 256 + c4 * 4) * 4,
                       g_Wt + (size_t)r * KK + kbase + c4 * 4);
        }
        if (tid < 32)
            cp_async16(smem_u32(xn_s) + tid * 16, g_xnorm + n0 + tid * 4);
        else if (tid < 96)
            cp_async16(smem_u32(wn_s) + (tid - 32) * 16,
                       g_wnorm + kbase + (tid - 32) * 4);
        CP_COMMIT();
        // W chunk 1 -> buf 1
        #pragma unroll
        for (int u = tid; u < 1024; u += 512) {
            int r = u >> 6, c4 = u & 63;
            cp_async16(ws_a + (uint32_t)(4096 + r * 256 + c4 * 4) * 4,
                       g_Wt + (size_t)(16 + r) * KK + kbase + c4 * 4);
        }
        CP_COMMIT();
    }

    ull acc[4][8];
    #pragma unroll
    for (int i = 0; i < 4; i++)
        #pragma unroll
        for (int j = 0; j < 8; j++) acc[i][j] = 0ULL;

    const int woff = kk2 * 128 + tc * 4;

    // ---- main loop: 16 chunks of 16 d-rows, triple buffered, 1 bar/chunk ----
    for (int ch = 0; ch < 16; ch++) {
        if (ch < 15) { CP_WAIT(1); } else { CP_WAIT(0); }
        __syncthreads();
        if (ch < 14) {
            // prefetch chunk ch+2 into buf (ch+2)%3
            uint32_t dst = ws_a + (uint32_t)(((ch + 2) % 3) * 4096) * 4;
            const float* src = g_Wt + (size_t)(ch + 2) * 16 * KK + kbase;
            #pragma unroll
            for (int u = tid; u < 1024; u += 512) {
                int r = u >> 6, c4 = u & 63;
                cp_async16(dst + (uint32_t)(r * 256 + c4 * 4) * 4,
                           src + (size_t)r * KK + c4 * 4);
            }
            CP_COMMIT();
        }

        const float* wb = ws + (ch % 3) * 4096;
        #pragma unroll 4
        for (int dl = 0; dl < 16; dl++) {
            const int d = (ch << 4) + dl;
            float4 wlo = *(const float4*)(wb + dl * 256 + woff);
            float4 whi = *(const float4*)(wb + dl * 256 + 64 + woff);
            ulonglong2 xa = *(const ulonglong2*)(xs + d * 128 + tr * 8);
            ulonglong2 xb = *(const ulonglong2*)(xs + d * 128 + tr * 8 + 4);
            ull W0, W1, W2, W3, W4, W5, W6, W7;
            PACK2(W0, __float_as_uint(wlo.x));
            PACK2(W1, __float_as_uint(wlo.y));
            PACK2(W2, __float_as_uint(wlo.z));
            PACK2(W3, __float_as_uint(wlo.w));
            PACK2(W4, __float_as_uint(whi.x));
            PACK2(W5, __float_as_uint(whi.y));
            PACK2(W6, __float_as_uint(whi.z));
            PACK2(W7, __float_as_uint(whi.w));
            FFMA2(acc[0][0], xa.x, W0); FFMA2(acc[1][0], xa.y, W0);
            FFMA2(acc[2][0], xb.x, W0); FFMA2(acc[3][0], xb.y, W0);
            FFMA2(acc[0][1], xa.x, W1); FFMA2(acc[1][1], xa.y, W1);
            FFMA2(acc[2][1], xb.x, W1); FFMA2(acc[3][1], xb.y, W1);
            FFMA2(acc[0][2], xa.x, W2); FFMA2(acc[1][2], xa.y, W2);
            FFMA2(acc[2][2], xb.x, W2); FFMA2(acc[3][2], xb.y, W2);
            FFMA2(acc[0][3], xa.x, W3); FFMA2(acc[1][3], xa.y, W3);
            FFMA2(acc[2][3], xb.x, W3); FFMA2(acc[3][3], xb.y, W3);
            FFMA2(acc[0][4], xa.x, W4); FFMA2(acc[1][4], xa.y, W4);
            FFMA2(acc[2][4], xb.x, W4); FFMA2(acc[3][4], xb.y, W4);
            FFMA2(acc[0][5], xa.x, W5); FFMA2(acc[1][5], xa.y, W5);
            FFMA2(acc[2][5], xb.x, W5); FFMA2(acc[3][5], xb.y, W5);
            FFMA2(acc[0][6], xa.x, W6); FFMA2(acc[1][6], xa.y, W6);
            FFMA2(acc[2][6], xb.x, W6); FFMA2(acc[3][6], xb.y, W6);
            FFMA2(acc[0][7], xa.x, W7); FFMA2(acc[1][7], xa.y, W7);
            FFMA2(acc[2][7], xb.x, W7); FFMA2(acc[3][7], xb.y, W7);
        }
    }

    // ---- epilogue: dist = fl(fl(xnorm - 2*dot) + wnorm), packed argmin ----
    ull best[8];
    #pragma unroll
    for (int r = 0; r < 8; r++) best[r] = 0xFFFFFFFFFFFFFFFFULL;

    #pragma unroll
    for (int i = 0; i < 4; i++) {
        int m0 = 8 * tr + 2 * i;
        float xn0 = xn_s[m0];
        float xn1 = xn_s[m0 + 1];
        #pragma unroll
        for (int j = 0; j < 8; j++) {
            int klocal = kk2 * 128 + ((j < 4) ? (tc * 4 + j) : (64 + tc * 4 + j - 4));
            float wn = wn_s[klocal];
            unsigned k = (unsigned)(kbase + klocal);
            float dot0 = __uint_as_float((unsigned)(acc[i][j] & 0xFFFFFFFFULL));
            float dot1 = __uint_as_float((unsigned)(acc[i][j] >> 32));
            float dist0 = __fadd_rn(__fmaf_rn(-2.0f, dot0, xn0), wn);
            float dist1 = __fadd_rn(__fmaf_rn(-2.0f, dot1, xn1), wn);
            ull p0 = ((ull)__float_as_uint(dist0) << 32) | k;
            ull p1 = ((ull)__float_as_uint(dist1) << 32) | k;
            if (p0 < best[2 * i])     best[2 * i]     = p0;
            if (p1 < best[2 * i + 1]) best[2 * i + 1] = p1;
        }
    }

    // reduce over the 16 code-lanes (lane bits 0..3), then global atomicMin
    #pragma unroll
    for (int r = 0; r < 8; r++) {
        ull v = best[r];
        #pragma unroll
        for (int ofs = 1; ofs < 16; ofs <<= 1) {
            ull o = __shfl_xor_sync(0xFFFFFFFFu, v, ofs);
            if (o < v) v = o;
        }
        best[r] = v;
    }
    if (tc == 0) {
        #pragma unroll
        for (int i = 0; i < 4; i++) {
            int m0 = 8 * tr + 2 * i;
            atomicMin(&g_best[n0 + m0],     best[2 * i]);
            atomicMin(&g_best[n0 + m0 + 1], best[2 * i + 1]);
        }
    }
}

// ---------------------------------------------------------
// quantize + straight-through + loss partial + index output
__global__ void __launch_bounds__(256)
vq_quant_kernel(const float* __restrict__ lat, const float* __restrict__ cb,
                float* __restrict__ out) {
    extern __shared__ float qsm[];
    float*    q_s   = qsm;                           // [64][256]
    unsigned* idx_s = (unsigned*)(qsm + 64 * 256);   // [64]
    float*    red   = (float*)(idx_s + 64);          // [256]

    const int tid = threadIdx.x;
    const int cid = blockIdx.x;     // 0..511
    const int b   = cid >> 4;
    const int t0  = (cid & 15) << 6;

    if (tid < 64) {
        int n = b * TT + t0 + tid;
        unsigned k = (unsigned)(g_best[n] & 0xFFFFFFFFULL);
        idx_s[tid] = k;
        out[OUT_IDX_OFF + n] = (float)k;
    }
    __syncthreads();

    {
        const float4* cb4 = (const float4*)cb;
        float4* q4 = (float4*)q_s;
        #pragma unroll
        for (int i = tid; i < 4096; i += 256) {
            int r = i >> 6, c = i & 63;
            q4[r * 64 + c] = cb4[idx_s[r] * 64 + c];
        }
    }
    __syncthreads();

    const int d = tid;
    const size_t base = ((size_t)b * DD + d) * TT + t0;
    float lsum = 0.0f;
    #pragma unroll 4
    for (int tt = 0; tt < 64; tt += 4) {
        float4 x4 = *(const float4*)(lat + base + tt);
        float q0 = q_s[(tt + 0) * 256 + d];
        float q1 = q_s[(tt + 1) * 256 + d];
        float q2 = q_s[(tt + 2) * 256 + d];
        float q3 = q_s[(tt + 3) * 256 + d];
        float d0 = __fsub_rn(q0, x4.x);
        float d1 = __fsub_rn(q1, x4.y);
        float d2 = __fsub_rn(q2, x4.z);
        float d3 = __fsub_rn(q3, x4.w);
        float4 st;
        st.x = __fadd_rn(x4.x, d0);
        st.y = __fadd_rn(x4.y, d1);
        st.z = __fadd_rn(x4.z, d2);
        st.w = __fadd_rn(x4.w, d3);
        *(float4*)(out + OUT_Q_OFF + base + tt) = st;
        lsum = __fmaf_rn(d0, d0, lsum);
        lsum = __fmaf_rn(d1, d1, lsum);
        lsum = __fmaf_rn(d2, d2, lsum);
        lsum = __fmaf_rn(d3, d3, lsum);
    }

    red[tid] = lsum;
    __syncthreads();
    for (int s = 128; s > 0; s >>= 1) {
        if (tid < s) red[tid] += red[tid + s];
        __syncthreads();
    }
    if (tid == 0) atomicAdd(&g_loss, (double)red[0]);
}

// ---------------------------------------------------------
__global__ void vq_finalize_kernel(float* __restrict__ out) {
    if (threadIdx.x == 0 && blockIdx.x == 0) {
        double mean = g_loss / (double)((size_t)NN * DD);
        out[OUT_LOSS_OFF] = (float)(mean * 1.25);
    }
}

// ---------------------------------------------------------
extern "C" void kernel_launch(void* const* d_in, const int* in_sizes, int n_in,
                              void* d_out, int out_size) {
    const float* lat = (const float*)d_in[0];   // [32, 256, 1024]
    const float* cb  = (const float*)d_in[1];   // [1024, 256]
    float* out = (float*)d_out;

    const int MAIN_SMEM  = (32768 + 3 * 4096 + 128 + 256) * 4;   // 181760 B
    const int QUANT_SMEM = (64 * 256 + 64 + 256) * 4 + 256;

    cudaFuncSetAttribute(vq_main_kernel,
                         cudaFuncAttributeMaxDynamicSharedMemorySize, MAIN_SMEM);
    cudaFuncSetAttribute(vq_quant_kernel,
                         cudaFuncAttributeMaxDynamicSharedMemorySize, QUANT_SMEM);

    vq_prep_w_kernel<<<KK, 256>>>(cb);
    vq_xnorm_kernel<<<NN / 256, 256>>>(lat);

    dim3 grid(256, 4);
    vq_main_kernel<<<grid, 512, MAIN_SMEM>>>(lat);

    vq_quant_kernel<<<512, 256, QUANT_SMEM>>>(lat, cb, out);
    vq_finalize_kernel<<<1, 1>>>(out);
}

// round 7
// speedup vs baseline: 2.6365x; 1.7921x over previous
#include <cuda_runtime.h>
#include <cuda_bf16.h>
#include <cstdint>

// Problem constants
#define BATCH 32
#define TT    1024
#define DD    256
#define KK    1024
#define NN    (BATCH*TT)
#define DT    (DD*TT)
#define KP    768            // K' = [x1|x1|x2] . [w1|w2|w1]

#define OUT_Q_OFF    0
#define OUT_LOSS_OFF 8388608
#define OUT_IDX_OFF  8388609

typedef unsigned long long ull;

// -------- device scratch (no allocations allowed) --------
__device__ __nv_bfloat16 g_A2[(size_t)NN * KP];   // token-major limbs [x1|x1|x2]
__device__ __nv_bfloat16 g_B2[(size_t)KK * KP];   // code limbs [w1|w2|w1]
__device__ float  g_Xt[(size_t)NN * DD];          // token-major fp32 latents
__device__ float  g_dist[(size_t)NN * KK];        // approx dist matrix
__device__ float  g_wnorm[KK];
__device__ float  g_xnorm[NN];
__device__ unsigned g_idx[NN];
__device__ double g_loss;

// -------- PTX helpers --------
__device__ __forceinline__ uint32_t smem_u32(const void* p) {
    uint32_t a;
    asm("{ .reg .u64 t; cvta.to.shared.u64 t, %1; cvt.u32.u64 %0, t; }"
        : "=r"(a) : "l"(p));
    return a;
}
__device__ __forceinline__ void cp_async16(uint32_t s, const void* g) {
    asm volatile("cp.async.cg.shared.global [%0], [%1], 16;" :: "r"(s), "l"(g));
}
#define CP_COMMIT() asm volatile("cp.async.commit_group;")
#define CP_WAIT1()  asm volatile("cp.async.wait_group 1;")
#define CP_WAIT0()  asm volatile("cp.async.wait_group 0;")

#define LDSM_X4(r0, r1, r2, r3, addr) \
    asm volatile("ldmatrix.sync.aligned.m8n8.x4.shared.b16 {%0,%1,%2,%3}, [%4];" \
        : "=r"(r0), "=r"(r1), "=r"(r2), "=r"(r3) : "r"(addr))

#define MMA_BF16(c, a, b0, b1) \
    asm volatile("mma.sync.aligned.m16n8k16.row.col.f32.bf16.bf16.f32 " \
        "{%0,%1,%2,%3}, {%4,%5,%6,%7}, {%8,%9}, {%0,%1,%2,%3};" \
        : "+f"((c)[0]), "+f"((c)[1]), "+f"((c)[2]), "+f"((c)[3]) \
        : "r"((a)[0]), "r"((a)[1]), "r"((a)[2]), "r"((a)[3]), "r"(b0), "r"(b1))

// ---------------------------------------------------------
// prep B: split codebook into bf16 limbs [w1|w2|w1] + wnorm; zero loss
__global__ void vq_prep_b_kernel(const float* __restrict__ cb) {
    __shared__ double sred[256];
    int k = blockIdx.x, d = threadIdx.x;
    float w = cb[k * DD + d];
    __nv_bfloat16 h1 = __float2bfloat16_rn(w);
    float r1 = __fsub_rn(w, __bfloat162float(h1));
    __nv_bfloat16 h2 = __float2bfloat16_rn(r1);
    size_t base = (size_t)k * KP;
    g_B2[base + d]       = h1;
    g_B2[base + 256 + d] = h2;
    g_B2[base + 512 + d] = h1;
    sred[d] = (double)w * (double)w;
    __syncthreads();
    for (int s = 128; s > 0; s >>= 1) {
        if (d < s) sred[d] += sred[d + s];
        __syncthreads();
    }
    if (d == 0) {
        g_wnorm[k] = (float)sred[0];
        if (k == 0) g_loss = 0.0;
    }
}

// prep A: transpose latents to token-major fp32 + bf16 limbs [x1|x1|x2],
// fused xnorm (fp64).
__global__ void __launch_bounds__(256)
vq_prep_a_kernel(const float* __restrict__ lat) {
    __shared__ float  s[256 * 33];
    __shared__ double pr[256];
    const int tid = threadIdx.x;
    const int b   = blockIdx.x >> 5;
    const int t0  = (blockIdx.x & 31) << 5;

    #pragma unroll
    for (int i = tid; i < 2048; i += 256) {
        int d = i >> 3, tq = i & 7;
        float4 v = *(const float4*)(lat + ((size_t)b * DD + d) * TT + t0 + tq * 4);
        s[d * 33 + tq * 4 + 0] = v.x;
        s[d * 33 + tq * 4 + 1] = v.y;
        s[d * 33 + tq * 4 + 2] = v.z;
        s[d * 33 + tq * 4 + 3] = v.w;
    }
    __syncthreads();

    const int d = tid;
    #pragma unroll 4
    for (int tl = 0; tl < 32; tl++) {
        size_t n = (size_t)b * TT + t0 + tl;
        float x = s[d * 33 + tl];
        __nv_bfloat16 h1 = __float2bfloat16_rn(x);
        float r1 = __fsub_rn(x, __bfloat162float(h1));
        __nv_bfloat16 h2 = __float2bfloat16_rn(r1);
        size_t base = n * KP;
        g_A2[base + d]       = h1;
        g_A2[base + 256 + d] = h1;
        g_A2[base + 512 + d] = h2;
        g_Xt[n * DD + d]     = x;
    }

    // fused xnorm: 8 d-groups x 32 tokens
    const int tk = tid & 31, dg = tid >> 5;
    double ssum = 0.0;
    #pragma unroll 8
    for (int dd = 0; dd < 32; dd++) {
        float v = s[(dg * 32 + dd) * 33 + tk];
        ssum += (double)v * (double)v;
    }
    pr[tid] = ssum;
    __syncthreads();
    if (tid < 32) {
        double tot = 0.0;
        #pragma unroll
        for (int j = 0; j < 8; j++) tot += pr[j * 32 + tid];
        g_xnorm[b * TT + t0 + tid] = (float)tot;
    }
}

// ---------------------------------------------------------
// main GEMM: CTA 128 tokens x 128 codes, K'=768 in 12 chunks of 64,
// mma.sync m16n8k16 bf16, double-buffered cp.async tiles (SW128 swizzle).
// Epilogue writes approx dist matrix.
#define SM_XN    65536
#define SM_WN    66048
#define SM_TOTM  66560

__device__ __forceinline__ void issue_chunk(uint32_t sb, int bufsel, int chunk,
                                            int n0, int kb, int tid) {
    uint32_t Ab = sb + (uint32_t)bufsel * 32768u;
    #pragma unroll
    for (int u = 0; u < 4; u++) {
        int j = tid + u * 256;
        int r = j >> 3, g8 = j & 7;
        cp_async16(Ab + (uint32_t)(r * 128 + ((g8 * 16) ^ ((r & 7) << 4))),
                   g_A2 + (size_t)(n0 + r) * KP + chunk * 64 + g8 * 8);
    }
    #pragma unroll
    for (int u = 0; u < 4; u++) {
        int j = tid + u * 256;
        int r = j >> 3, g8 = j & 7;
        cp_async16(Ab + 16384u + (uint32_t)(r * 128 + ((g8 * 16) ^ ((r & 7) << 4))),
                   g_B2 + (size_t)(kb + r) * KP + chunk * 64 + g8 * 8);
    }
}

__global__ void __launch_bounds__(256, 2)
vq_mma_kernel() {
    extern __shared__ char smc[];
    const uint32_t sb = smem_u32(smc);
    float* xn_s = (float*)(smc + SM_XN);
    float* wn_s = (float*)(smc + SM_WN);

    const int tid  = threadIdx.x;
    const int lane = tid & 31;
    const int warp = tid >> 5;
    const int wm   = warp >> 1;        // 0..3
    const int wnn  = warp & 1;         // 0..1
    const int n0   = blockIdx.x << 7;  // token base
    const int kb   = blockIdx.y << 7;  // code base

    if (tid < 128) xn_s[tid] = g_xnorm[n0 + tid];
    else           wn_s[tid - 128] = g_wnorm[kb + tid - 128];

    issue_chunk(sb, 0, 0, n0, kb, tid); CP_COMMIT();
    issue_chunk(sb, 1, 1, n0, kb, tid); CP_COMMIT();

    float acc[2][8][4];
    #pragma unroll
    for (int i = 0; i < 2; i++)
        #pragma unroll
        for (int j = 0; j < 8; j++)
            #pragma unroll
            for (int e = 0; e < 4; e++) acc[i][j][e] = 0.0f;

    const int arow   = (lane & 7) | (((lane >> 3) & 1) << 3);
    const int akoffB = (lane >> 4) << 4;
    const int brow   = (lane & 7) | ((lane >> 4) << 3);
    const int bkoffB = ((lane >> 3) & 1) << 4;

    for (int c = 0; c < 12; c++) {
        if (c < 11) { CP_WAIT1(); } else { CP_WAIT0(); }
        __syncthreads();

        uint32_t Ab = sb + (uint32_t)(c & 1) * 32768u;
        uint32_t Bb = Ab + 16384u;

        #pragma unroll
        for (int k16 = 0; k16 < 4; k16++) {
            uint32_t a[2][4];
            #pragma unroll
            for (int mt = 0; mt < 2; mt++) {
                int r = wm * 32 + mt * 16 + arow;
                uint32_t ad = Ab + (uint32_t)(r * 128 +
                              ((k16 * 32 + akoffB) ^ ((r & 7) << 4)));
                LDSM_X4(a[mt][0], a[mt][1], a[mt][2], a[mt][3], ad);
            }
            uint32_t bf[8][2];
            #pragma unroll
            for (int p = 0; p < 4; p++) {
                int nl = wnn * 64 + p * 16 + brow;
                uint32_t bd = Bb + (uint32_t)(nl * 128 +
                              ((k16 * 32 + bkoffB) ^ ((nl & 7) << 4)));
                LDSM_X4(bf[2 * p][0], bf[2 * p][1], bf[2 * p + 1][0], bf[2 * p + 1][1], bd);
            }
            #pragma unroll
            for (int mt = 0; mt < 2; mt++)
                #pragma unroll
                for (int n8 = 0; n8 < 8; n8++)
                    MMA_BF16(acc[mt][n8], a[mt], bf[n8][0], bf[n8][1]);
        }
        __syncthreads();
        if (c < 10) { issue_chunk(sb, c & 1, c + 2, n0, kb, tid); CP_COMMIT(); }
    }

    // ---- epilogue: approx dist = fl(fl(xn - 2*dot) + wn) -> g_dist ----
    const int g  = lane >> 2;
    const int qc = lane & 3;
    #pragma unroll
    for (int mt = 0; mt < 2; mt++) {
        #pragma unroll
        for (int h = 0; h < 2; h++) {
            int rl = wm * 32 + mt * 16 + h * 8 + g;
            float xn = xn_s[rl];
            float* rowp = g_dist + (size_t)(n0 + rl) * KK + kb + wnn * 64;
            #pragma unroll
            for (int n8 = 0; n8 < 8; n8++) {
                int cl0 = wnn * 64 + n8 * 8 + qc * 2;
                float d0 = __fadd_rn(__fmaf_rn(-2.0f, acc[mt][n8][h * 2 + 0], xn),
                                     wn_s[cl0]);
                float d1 = __fadd_rn(__fmaf_rn(-2.0f, acc[mt][n8][h * 2 + 1], xn),
                                     wn_s[cl0 + 1]);
                ((float2*)rowp)[n8 * 4 + qc] = make_float2(d0, d1);
            }
        }
    }
}

// ---------------------------------------------------------
// select: warp per token. Scan approx dists, candidates within EPS of min,
// exact fp32 recheck with reference dist formula, first-index tie-break.
#define EPS_SEL 2e-4f

__global__ void __launch_bounds__(256)
vq_select_kernel(const float* __restrict__ cb) {
    const int wid  = threadIdx.x >> 5;
    const int lane = threadIdx.x & 31;
    const int n    = blockIdx.x * 8 + wid;

    const float4* drow = (const float4*)(g_dist + (size_t)n * KK);
    float4 v[8];
    float m = 3.4e38f;
    #pragma unroll
    for (int j = 0; j < 8; j++) {
        v[j] = drow[lane + j * 32];
        m = fminf(m, fminf(fminf(v[j].x, v[j].y), fminf(v[j].z, v[j].w)));
    }
    #pragma unroll
    for (int o = 16; o; o >>= 1) m = fminf(m, __shfl_xor_sync(0xFFFFFFFFu, m, o));
    const float thresh = m + EPS_SEL;

    unsigned cmask = 0;
    #pragma unroll
    for (int j = 0; j < 8; j++) {
        if (v[j].x <= thresh) cmask |= 1u << (j * 4 + 0);
        if (v[j].y <= thresh) cmask |= 1u << (j * 4 + 1);
        if (v[j].z <= thresh) cmask |= 1u << (j * 4 + 2);
        if (v[j].w <= thresh) cmask |= 1u << (j * 4 + 3);
    }

    const float xn = g_xnorm[n];
    const float4* xr = (const float4*)(g_Xt + (size_t)n * DD);
    float4 xa = xr[lane];
    float4 xb = xr[32 + lane];

    ull bestp = 0xFFFFFFFFFFFFFFFFULL;
    unsigned act;
    while ((act = __ballot_sync(0xFFFFFFFFu, cmask != 0)) != 0) {
        int leader = __ffs(act) - 1;
        int k = 0;
        if (lane == leader) {
            int bpos = __ffs(cmask) - 1;
            cmask &= cmask - 1;
            k = 4 * lane + (bpos >> 2) * 128 + (bpos & 3);
        }
        k = __shfl_sync(0xFFFFFFFFu, k, leader);

        const float4* wr = (const float4*)(cb + (size_t)k * DD);
        float4 wa = wr[lane];
        float4 wb = wr[32 + lane];
        float s = 0.0f;
        s = __fmaf_rn(xa.x, wa.x, s); s = __fmaf_rn(xa.y, wa.y, s);
        s = __fmaf_rn(xa.z, wa.z, s); s = __fmaf_rn(xa.w, wa.w, s);
        s = __fmaf_rn(xb.x, wb.x, s); s = __fmaf_rn(xb.y, wb.y, s);
        s = __fmaf_rn(xb.z, wb.z, s); s = __fmaf_rn(xb.w, wb.w, s);
        #pragma unroll
        for (int o = 16; o; o >>= 1) s = __fadd_rn(s, __shfl_xor_sync(0xFFFFFFFFu, s, o));

        float dist = __fadd_rn(__fmaf_rn(-2.0f, s, xn), g_wnorm[k]);
        ull p = ((ull)__float_as_uint(dist) << 32) | (unsigned)k;
        if (p < bestp) bestp = p;
    }
    if (lane == 0) g_idx[n] = (unsigned)(bestp & 0xFFFFFFFFULL);
}

// ---------------------------------------------------------
// quantize + straight-through + loss + indices (coalesced along t)
__global__ void __launch_bounds__(256)
vq_quant_kernel(const float* __restrict__ lat, const float* __restrict__ cb,
                float* __restrict__ out) {
    extern __shared__ float qsm[];
    float*    q_s   = qsm;                             // [64][257]
    unsigned* idx_s = (unsigned*)(qsm + 64 * 257);     // [64]
    float*    red   = (float*)(idx_s + 64);            // [256]

    const int tid = threadIdx.x;
    const int cid = blockIdx.x;      // 0..511
    const int b   = cid >> 4;
    const int t0  = (cid & 15) << 6;

    if (tid < 64) {
        int n = b * TT + t0 + tid;
        unsigned k = g_idx[n];
        idx_s[tid] = k;
        out[OUT_IDX_OFF + n] = (float)k;
    }
    __syncthreads();

    {
        const float4* cb4 = (const float4*)cb;
        #pragma unroll
        for (int i = tid; i < 4096; i += 256) {
            int r = i >> 6, c4 = i & 63;
            float4 v = cb4[idx_s[r] * 64 + c4];
            float* q = q_s + r * 257 + c4 * 4;
            q[0] = v.x; q[1] = v.y; q[2] = v.z; q[3] = v.w;
        }
    }
    __syncthreads();

    const int tl = tid & 63;
    const int dg = tid >> 6;
    const int t  = t0 + tl;
    float lsum = 0.0f;
    #pragma unroll 8
    for (int dd = 0; dd < 64; dd++) {
        int d = dg * 64 + dd;
        size_t off = ((size_t)b * DD + d) * TT + t;
        float x = lat[off];
        float q = q_s[tl * 257 + d];
        float dq = __fsub_rn(q, x);
        out[OUT_Q_OFF + off] = __fadd_rn(x, dq);
        lsum = __fmaf_rn(dq, dq, lsum);
    }

    red[tid] = lsum;
    __syncthreads();
    for (int s = 128; s > 0; s >>= 1) {
        if (tid < s) red[tid] += red[tid + s];
        __syncthreads();
    }
    if (tid == 0) atomicAdd(&g_loss, (double)red[0]);
}

// ---------------------------------------------------------
__global__ void vq_finalize_kernel(float* __restrict__ out) {
    if (threadIdx.x == 0 && blockIdx.x == 0) {
        double mean = g_loss / (double)((size_t)NN * DD);
        out[OUT_LOSS_OFF] = (float)(mean * 1.25);
    }
}

// ---------------------------------------------------------
extern "C" void kernel_launch(void* const* d_in, const int* in_sizes, int n_in,
                              void* d_out, int out_size) {
    const float* lat = (const float*)d_in[0];   // [32, 256, 1024]
    const float* cb  = (const float*)d_in[1];   // [1024, 256]
    float* out = (float*)d_out;

    const int QUANT_SMEM = (64 * 257 + 64 + 256) * 4;   // 67072 B

    cudaFuncSetAttribute(vq_mma_kernel,
                         cudaFuncAttributeMaxDynamicSharedMemorySize, SM_TOTM);
    cudaFuncSetAttribute(vq_quant_kernel,
                         cudaFuncAttributeMaxDynamicSharedMemorySize, QUANT_SMEM);

    vq_prep_b_kernel<<<KK, 256>>>(cb);
    vq_prep_a_kernel<<<1024, 256>>>(lat);

    dim3 grid(256, 8);
    vq_mma_kernel<<<grid, 256, SM_TOTM>>>();

    vq_select_kernel<<<NN / 8, 256>>>(cb);
    vq_quant_kernel<<<512, 256, QUANT_SMEM>>>(lat, cb, out);
    vq_finalize_kernel<<<1, 1>>>(out);
}

// round 8
// speedup vs baseline: 3.6139x; 1.3707x over previous
#include <cuda_runtime.h>
#include <cuda_bf16.h>
#include <cstdint>

// Problem constants
#define BATCH 32
#define TT    1024
#define DD    256
#define KK    1024
#define NN    (BATCH*TT)
#define DT    (DD*TT)

#define OUT_Q_OFF    0
#define OUT_LOSS_OFF 8388608
#define OUT_IDX_OFF  8388609

typedef unsigned long long ull;

// -------- device scratch (no allocations allowed) --------
__device__ __nv_bfloat16 g_A2[(size_t)NN * DD];   // token-major bf16 latents
__device__ __nv_bfloat16 g_B2[(size_t)KK * DD];   // bf16 codebook
__device__ float  g_Xt[(size_t)NN * DD];          // token-major fp32 latents
__device__ float  g_dist[(size_t)NN * KK];        // approx dist matrix
__device__ float  g_wnorm[KK];
__device__ float  g_xnorm[NN];
__device__ unsigned g_idx[NN];
__device__ double g_loss;

// -------- PTX helpers --------
__device__ __forceinline__ uint32_t smem_u32(const void* p) {
    uint32_t a;
    asm("{ .reg .u64 t; cvta.to.shared.u64 t, %1; cvt.u32.u64 %0, t; }"
        : "=r"(a) : "l"(p));
    return a;
}
__device__ __forceinline__ void cp_async16(uint32_t s, const void* g) {
    asm volatile("cp.async.cg.shared.global [%0], [%1], 16;" :: "r"(s), "l"(g));
}
#define CP_COMMIT() asm volatile("cp.async.commit_group;")
#define CP_WAIT1()  asm volatile("cp.async.wait_group 1;")
#define CP_WAIT0()  asm volatile("cp.async.wait_group 0;")

#define LDSM_X4(r0, r1, r2, r3, addr) \
    asm volatile("ldmatrix.sync.aligned.m8n8.x4.shared.b16 {%0,%1,%2,%3}, [%4];" \
        : "=r"(r0), "=r"(r1), "=r"(r2), "=r"(r3) : "r"(addr))

#define MMA_BF16(c, a, b0, b1) \
    asm volatile("mma.sync.aligned.m16n8k16.row.col.f32.bf16.bf16.f32 " \
        "{%0,%1,%2,%3}, {%4,%5,%6,%7}, {%8,%9}, {%0,%1,%2,%3};" \
        : "+f"((c)[0]), "+f"((c)[1]), "+f"((c)[2]), "+f"((c)[3]) \
        : "r"((a)[0]), "r"((a)[1]), "r"((a)[2]), "r"((a)[3]), "r"(b0), "r"(b1))

// ---------------------------------------------------------
// prep B: bf16 codebook + wnorm; zero loss
__global__ void vq_prep_b_kernel(const float* __restrict__ cb) {
    __shared__ double sred[256];
    int k = blockIdx.x, d = threadIdx.x;
    float w = cb[k * DD + d];
    g_B2[(size_t)k * DD + d] = __float2bfloat16_rn(w);
    sred[d] = (double)w * (double)w;
    __syncthreads();
    for (int s = 128; s > 0; s >>= 1) {
        if (d < s) sred[d] += sred[d + s];
        __syncthreads();
    }
    if (d == 0) {
        g_wnorm[k] = (float)sred[0];
        if (k == 0) g_loss = 0.0;
    }
}

// prep A: transpose latents to token-major fp32 + bf16, fused xnorm (fp64).
__global__ void __launch_bounds__(256)
vq_prep_a_kernel(const float* __restrict__ lat) {
    __shared__ float  s[256 * 33];
    __shared__ double pr[256];
    const int tid = threadIdx.x;
    const int b   = blockIdx.x >> 5;
    const int t0  = (blockIdx.x & 31) << 5;

    #pragma unroll
    for (int i = tid; i < 2048; i += 256) {
        int d = i >> 3, tq = i & 7;
        float4 v = *(const float4*)(lat + ((size_t)b * DD + d) * TT + t0 + tq * 4);
        s[d * 33 + tq * 4 + 0] = v.x;
        s[d * 33 + tq * 4 + 1] = v.y;
        s[d * 33 + tq * 4 + 2] = v.z;
        s[d * 33 + tq * 4 + 3] = v.w;
    }
    __syncthreads();

    const int d = tid;
    #pragma unroll 4
    for (int tl = 0; tl < 32; tl++) {
        size_t n = (size_t)b * TT + t0 + tl;
        float x = s[d * 33 + tl];
        g_A2[n * DD + d] = __float2bfloat16_rn(x);
        g_Xt[n * DD + d] = x;
    }

    // fused xnorm: 8 d-groups x 32 tokens
    const int tk = tid & 31, dg = tid >> 5;
    double ssum = 0.0;
    #pragma unroll 8
    for (int dd = 0; dd < 32; dd++) {
        float v = s[(dg * 32 + dd) * 33 + tk];
        ssum += (double)v * (double)v;
    }
    pr[tid] = ssum;
    __syncthreads();
    if (tid < 32) {
        double tot = 0.0;
        #pragma unroll
        for (int j = 0; j < 8; j++) tot += pr[j * 32 + tid];
        g_xnorm[b * TT + t0 + tid] = (float)tot;
    }
}

// ---------------------------------------------------------
// main GEMM: CTA 128 tokens x 128 codes, K=256 in 4 chunks of 64,
// mma.sync m16n8k16 bf16, double-buffered cp.async tiles (SW128 swizzle).
// Epilogue writes approx dist matrix.
#define SM_XN    65536
#define SM_WN    66048
#define SM_TOTM  66560

__device__ __forceinline__ void issue_chunk(uint32_t sb, int bufsel, int chunk,
                                            int n0, int kb, int tid) {
    uint32_t Ab = sb + (uint32_t)bufsel * 32768u;
    #pragma unroll
    for (int u = 0; u < 4; u++) {
        int j = tid + u * 256;
        int r = j >> 3, g8 = j & 7;
        cp_async16(Ab + (uint32_t)(r * 128 + ((g8 * 16) ^ ((r & 7) << 4))),
                   g_A2 + (size_t)(n0 + r) * DD + chunk * 64 + g8 * 8);
    }
    #pragma unroll
    for (int u = 0; u < 4; u++) {
        int j = tid + u * 256;
        int r = j >> 3, g8 = j & 7;
        cp_async16(Ab + 16384u + (uint32_t)(r * 128 + ((g8 * 16) ^ ((r & 7) << 4))),
                   g_B2 + (size_t)(kb + r) * DD + chunk * 64 + g8 * 8);
    }
}

__global__ void __launch_bounds__(256, 2)
vq_mma_kernel() {
    extern __shared__ char smc[];
    const uint32_t sb = smem_u32(smc);
    float* xn_s = (float*)(smc + SM_XN);
    float* wn_s = (float*)(smc + SM_WN);

    const int tid  = threadIdx.x;
    const int lane = tid & 31;
    const int warp = tid >> 5;
    const int wm   = warp >> 1;        // 0..3
    const int wnn  = warp & 1;         // 0..1
    const int n0   = blockIdx.x << 7;  // token base
    const int kb   = blockIdx.y << 7;  // code base

    if (tid < 128) xn_s[tid] = g_xnorm[n0 + tid];
    else           wn_s[tid - 128] = g_wnorm[kb + tid - 128];

    issue_chunk(sb, 0, 0, n0, kb, tid); CP_COMMIT();
    issue_chunk(sb, 1, 1, n0, kb, tid); CP_COMMIT();

    float acc[2][8][4];
    #pragma unroll
    for (int i = 0; i < 2; i++)
        #pragma unroll
        for (int j = 0; j < 8; j++)
            #pragma unroll
            for (int e = 0; e < 4; e++) acc[i][j][e] = 0.0f;

    const int arow   = (lane & 7) | (((lane >> 3) & 1) << 3);
    const int akoffB = (lane >> 4) << 4;
    const int brow   = (lane & 7) | ((lane >> 4) << 3);
    const int bkoffB = ((lane >> 3) & 1) << 4;

    for (int c = 0; c < 4; c++) {
        if (c < 3) { CP_WAIT1(); } else { CP_WAIT0(); }
        __syncthreads();

        uint32_t Ab = sb + (uint32_t)(c & 1) * 32768u;
        uint32_t Bb = Ab + 16384u;

        #pragma unroll
        for (int k16 = 0; k16 < 4; k16++) {
            uint32_t a[2][4];
            #pragma unroll
            for (int mt = 0; mt < 2; mt++) {
                int r = wm * 32 + mt * 16 + arow;
                uint32_t ad = Ab + (uint32_t)(r * 128 +
                              ((k16 * 32 + akoffB) ^ ((r & 7) << 4)));
                LDSM_X4(a[mt][0], a[mt][1], a[mt][2], a[mt][3], ad);
            }
            uint32_t bf[8][2];
            #pragma unroll
            for (int p = 0; p < 4; p++) {
                int nl = wnn * 64 + p * 16 + brow;
                uint32_t bd = Bb + (uint32_t)(nl * 128 +
                              ((k16 * 32 + bkoffB) ^ ((nl & 7) << 4)));
                LDSM_X4(bf[2 * p][0], bf[2 * p][1], bf[2 * p + 1][0], bf[2 * p + 1][1], bd);
            }
            #pragma unroll
            for (int mt = 0; mt < 2; mt++)
                #pragma unroll
                for (int n8 = 0; n8 < 8; n8++)
                    MMA_BF16(acc[mt][n8], a[mt], bf[n8][0], bf[n8][1]);
        }
        __syncthreads();
        if (c < 2) { issue_chunk(sb, c & 1, c + 2, n0, kb, tid); CP_COMMIT(); }
    }

    // ---- epilogue: approx dist = fl(fl(xn - 2*dot) + wn) -> g_dist ----
    const int g  = lane >> 2;
    const int qc = lane & 3;
    #pragma unroll
    for (int mt = 0; mt < 2; mt++) {
        #pragma unroll
        for (int h = 0; h < 2; h++) {
            int rl = wm * 32 + mt * 16 + h * 8 + g;
            float xn = xn_s[rl];
            float* rowp = g_dist + (size_t)(n0 + rl) * KK + kb + wnn * 64;
            #pragma unroll
            for (int n8 = 0; n8 < 8; n8++) {
                int cl0 = wnn * 64 + n8 * 8 + qc * 2;
                float d0 = __fadd_rn(__fmaf_rn(-2.0f, acc[mt][n8][h * 2 + 0], xn),
                                     wn_s[cl0]);
                float d1 = __fadd_rn(__fmaf_rn(-2.0f, acc[mt][n8][h * 2 + 1], xn),
                                     wn_s[cl0 + 1]);
                ((float2*)rowp)[n8 * 4 + qc] = make_float2(d0, d1);
            }
        }
    }
}

// ---------------------------------------------------------
// select: warp per token. Scan approx dists, candidates within EPS of min,
// exact fp32 recheck with reference dist formula, first-index tie-break.
// EPS = 1e-2 >= 2x the deterministic Cauchy-Schwarz bf16 error bound (~5e-3).
#define EPS_SEL 1e-2f

__global__ void __launch_bounds__(256)
vq_select_kernel(const float* __restrict__ cb) {
    const int wid  = threadIdx.x >> 5;
    const int lane = threadIdx.x & 31;
    const int n    = blockIdx.x * 8 + wid;

    const float4* drow = (const float4*)(g_dist + (size_t)n * KK);
    float4 v[8];
    float m = 3.4e38f;
    #pragma unroll
    for (int j = 0; j < 8; j++) {
        v[j] = drow[lane + j * 32];
        m = fminf(m, fminf(fminf(v[j].x, v[j].y), fminf(v[j].z, v[j].w)));
    }
    #pragma unroll
    for (int o = 16; o; o >>= 1) m = fminf(m, __shfl_xor_sync(0xFFFFFFFFu, m, o));
    const float thresh = m + EPS_SEL;

    unsigned cmask = 0;
    #pragma unroll
    for (int j = 0; j < 8; j++) {
        if (v[j].x <= thresh) cmask |= 1u << (j * 4 + 0);
        if (v[j].y <= thresh) cmask |= 1u << (j * 4 + 1);
        if (v[j].z <= thresh) cmask |= 1u << (j * 4 + 2);
        if (v[j].w <= thresh) cmask |= 1u << (j * 4 + 3);
    }

    const float xn = g_xnorm[n];
    const float4* xr = (const float4*)(g_Xt + (size_t)n * DD);
    float4 xa = xr[lane];
    float4 xb = xr[32 + lane];

    ull bestp = 0xFFFFFFFFFFFFFFFFULL;
    unsigned act;
    while ((act = __ballot_sync(0xFFFFFFFFu, cmask != 0)) != 0) {
        int leader = __ffs(act) - 1;
        int k = 0;
        if (lane == leader) {
            int bpos = __ffs(cmask) - 1;
            cmask &= cmask - 1;
            k = 4 * lane + (bpos >> 2) * 128 + (bpos & 3);
        }
        k = __shfl_sync(0xFFFFFFFFu, k, leader);

        const float4* wr = (const float4*)(cb + (size_t)k * DD);
        float4 wa = wr[lane];
        float4 wb = wr[32 + lane];
        float s = 0.0f;
        s = __fmaf_rn(xa.x, wa.x, s); s = __fmaf_rn(xa.y, wa.y, s);
        s = __fmaf_rn(xa.z, wa.z, s); s = __fmaf_rn(xa.w, wa.w, s);
        s = __fmaf_rn(xb.x, wb.x, s); s = __fmaf_rn(xb.y, wb.y, s);
        s = __fmaf_rn(xb.z, wb.z, s); s = __fmaf_rn(xb.w, wb.w, s);
        #pragma unroll
        for (int o = 16; o; o >>= 1) s = __fadd_rn(s, __shfl_xor_sync(0xFFFFFFFFu, s, o));

        float dist = __fadd_rn(__fmaf_rn(-2.0f, s, xn), g_wnorm[k]);
        ull p = ((ull)__float_as_uint(dist) << 32) | (unsigned)k;
        if (p < bestp) bestp = p;
    }
    if (lane == 0) g_idx[n] = (unsigned)(bestp & 0xFFFFFFFFULL);
}

// ---------------------------------------------------------
// quantize + straight-through + loss + indices (coalesced along t)
__global__ void __launch_bounds__(256)
vq_quant_kernel(const float* __restrict__ lat, const float* __restrict__ cb,
                float* __restrict__ out) {
    extern __shared__ float qsm[];
    float*    q_s   = qsm;                             // [64][257]
    unsigned* idx_s = (unsigned*)(qsm + 64 * 257);     // [64]
    float*    red   = (float*)(idx_s + 64);            // [256]

    const int tid = threadIdx.x;
    const int cid = blockIdx.x;      // 0..511
    const int b   = cid >> 4;
    const int t0  = (cid & 15) << 6;

    if (tid < 64) {
        int n = b * TT + t0 + tid;
        unsigned k = g_idx[n];
        idx_s[tid] = k;
        out[OUT_IDX_OFF + n] = (float)k;
    }
    __syncthreads();

    {
        const float4* cb4 = (const float4*)cb;
        #pragma unroll
        for (int i = tid; i < 4096; i += 256) {
            int r = i >> 6, c4 = i & 63;
            float4 v = cb4[idx_s[r] * 64 + c4];
            float* q = q_s + r * 257 + c4 * 4;
            q[0] = v.x; q[1] = v.y; q[2] = v.z; q[3] = v.w;
        }
    }
    __syncthreads();

    const int tl = tid & 63;
    const int dg = tid >> 6;
    const int t  = t0 + tl;
    float lsum = 0.0f;
    #pragma unroll 8
    for (int dd = 0; dd < 64; dd++) {
        int d = dg * 64 + dd;
        size_t off = ((size_t)b * DD + d) * TT + t;
        float x = lat[off];
        float q = q_s[tl * 257 + d];
        float dq = __fsub_rn(q, x);
        out[OUT_Q_OFF + off] = __fadd_rn(x, dq);
        lsum = __fmaf_rn(dq, dq, lsum);
    }

    red[tid] = lsum;
    __syncthreads();
    for (int s = 128; s > 0; s >>= 1) {
        if (tid < s) red[tid] += red[tid + s];
        __syncthreads();
    }
    if (tid == 0) atomicAdd(&g_loss, (double)red[0]);
}

// ---------------------------------------------------------
__global__ void vq_finalize_kernel(float* __restrict__ out) {
    if (threadIdx.x == 0 && blockIdx.x == 0) {
        double mean = g_loss / (double)((size_t)NN * DD);
        out[OUT_LOSS_OFF] = (float)(mean * 1.25);
    }
}

// ---------------------------------------------------------
extern "C" void kernel_launch(void* const* d_in, const int* in_sizes, int n_in,
                              void* d_out, int out_size) {
    const float* lat = (const float*)d_in[0];   // [32, 256, 1024]
    const float* cb  = (const float*)d_in[1];   // [1024, 256]
    float* out = (float*)d_out;

    const int QUANT_SMEM = (64 * 257 + 64 + 256) * 4;   // 67072 B

    cudaFuncSetAttribute(vq_mma_kernel,
                         cudaFuncAttributeMaxDynamicSharedMemorySize, SM_TOTM);
    cudaFuncSetAttribute(vq_quant_kernel,
                         cudaFuncAttributeMaxDynamicSharedMemorySize, QUANT_SMEM);

    vq_prep_b_kernel<<<KK, 256>>>(cb);
    vq_prep_a_kernel<<<1024, 256>>>(lat);

    dim3 grid(256, 8);
    vq_mma_kernel<<<grid, 256, SM_TOTM>>>();

    vq_select_kernel<<<NN / 8, 256>>>(cb);
    vq_quant_kernel<<<512, 256, QUANT_SMEM>>>(lat, cb, out);
    vq_finalize_kernel<<<1, 1>>>(out);
}

// round 9
// speedup vs baseline: 3.8440x; 1.0637x over previous
#include <cuda_runtime.h>
#include <cuda_bf16.h>
#include <cuda_fp16.h>
#include <cstdint>

// Problem constants
#define BATCH 32
#define TT    1024
#define DD    256
#define KK    1024
#define NN    (BATCH*TT)
#define DT    (DD*TT)

#define OUT_Q_OFF    0
#define OUT_LOSS_OFF 8388608
#define OUT_IDX_OFF  8388609

typedef unsigned long long ull;

// -------- device scratch (no allocations allowed) --------
__device__ __nv_bfloat16 g_A2[(size_t)NN * DD];   // token-major bf16 latents
__device__ __nv_bfloat16 g_B2[(size_t)KK * DD];   // bf16 codebook
__device__ float  g_Xt[(size_t)NN * DD];          // token-major fp32 latents
__device__ __half g_s[(size_t)NN * KK];           // approx s = wn - 2*dot (fp16)
__device__ float  g_wnorm[KK];
__device__ float  g_xnorm[NN];
__device__ unsigned g_idx[NN];
__device__ double g_loss;

// -------- PTX helpers --------
__device__ __forceinline__ uint32_t smem_u32(const void* p) {
    uint32_t a;
    asm("{ .reg .u64 t; cvta.to.shared.u64 t, %1; cvt.u32.u64 %0, t; }"
        : "=r"(a) : "l"(p));
    return a;
}
__device__ __forceinline__ void cp_async16(uint32_t s, const void* g) {
    asm volatile("cp.async.cg.shared.global [%0], [%1], 16;" :: "r"(s), "l"(g));
}
#define CP_COMMIT() asm volatile("cp.async.commit_group;")
#define CP_WAIT1()  asm volatile("cp.async.wait_group 1;")
#define CP_WAIT0()  asm volatile("cp.async.wait_group 0;")

#define LDSM_X4(r0, r1, r2, r3, addr) \
    asm volatile("ldmatrix.sync.aligned.m8n8.x4.shared.b16 {%0,%1,%2,%3}, [%4];" \
        : "=r"(r0), "=r"(r1), "=r"(r2), "=r"(r3) : "r"(addr))

#define MMA_BF16(c, a, b0, b1) \
    asm volatile("mma.sync.aligned.m16n8k16.row.col.f32.bf16.bf16.f32 " \
        "{%0,%1,%2,%3}, {%4,%5,%6,%7}, {%8,%9}, {%0,%1,%2,%3};" \
        : "+f"((c)[0]), "+f"((c)[1]), "+f"((c)[2]), "+f"((c)[3]) \
        : "r"((a)[0]), "r"((a)[1]), "r"((a)[2]), "r"((a)[3]), "r"(b0), "r"(b1))

// ---------------------------------------------------------
// prep B: bf16 codebook + wnorm; zero loss
__global__ void vq_prep_b_kernel(const float* __restrict__ cb) {
    __shared__ double sred[256];
    int k = blockIdx.x, d = threadIdx.x;
    float w = cb[k * DD + d];
    g_B2[(size_t)k * DD + d] = __float2bfloat16_rn(w);
    sred[d] = (double)w * (double)w;
    __syncthreads();
    for (int s = 128; s > 0; s >>= 1) {
        if (d < s) sred[d] += sred[d + s];
        __syncthreads();
    }
    if (d == 0) {
        g_wnorm[k] = (float)sred[0];
        if (k == 0) g_loss = 0.0;
    }
}

// prep A: transpose latents to token-major fp32 + bf16, fused xnorm (fp64).
__global__ void __launch_bounds__(256)
vq_prep_a_kernel(const float* __restrict__ lat) {
    __shared__ float  s[256 * 33];
    __shared__ double pr[256];
    const int tid = threadIdx.x;
    const int b   = blockIdx.x >> 5;
    const int t0  = (blockIdx.x & 31) << 5;

    #pragma unroll
    for (int i = tid; i < 2048; i += 256) {
        int d = i >> 3, tq = i & 7;
        float4 v = *(const float4*)(lat + ((size_t)b * DD + d) * TT + t0 + tq * 4);
        s[d * 33 + tq * 4 + 0] = v.x;
        s[d * 33 + tq * 4 + 1] = v.y;
        s[d * 33 + tq * 4 + 2] = v.z;
        s[d * 33 + tq * 4 + 3] = v.w;
    }
    __syncthreads();

    const int d = tid;
    #pragma unroll 4
    for (int tl = 0; tl < 32; tl++) {
        size_t n = (size_t)b * TT + t0 + tl;
        float x = s[d * 33 + tl];
        g_A2[n * DD + d] = __float2bfloat16_rn(x);
        g_Xt[n * DD + d] = x;
    }

    const int tk = tid & 31, dg = tid >> 5;
    double ssum = 0.0;
    #pragma unroll 8
    for (int dd = 0; dd < 32; dd++) {
        float v = s[(dg * 32 + dd) * 33 + tk];
        ssum += (double)v * (double)v;
    }
    pr[tid] = ssum;
    __syncthreads();
    if (tid < 32) {
        double tot = 0.0;
        #pragma unroll
        for (int j = 0; j < 8; j++) tot += pr[j * 32 + tid];
        g_xnorm[b * TT + t0 + tid] = (float)tot;
    }
}

// ---------------------------------------------------------
// main GEMM: CTA 128 tokens x 128 codes, K=256 in 4 chunks of 64,
// mma.sync m16n8k16 bf16, double-buffered cp.async tiles (SW128 swizzle).
// Epilogue writes fp16 surrogate s = wn - 2*dot.
#define SM_WN    65536
#define SM_TOTM  66048

__device__ __forceinline__ void issue_chunk(uint32_t sb, int bufsel, int chunk,
                                            int n0, int kb, int tid) {
    uint32_t Ab = sb + (uint32_t)bufsel * 32768u;
    #pragma unroll
    for (int u = 0; u < 4; u++) {
        int j = tid + u * 256;
        int r = j >> 3, g8 = j & 7;
        cp_async16(Ab + (uint32_t)(r * 128 + ((g8 * 16) ^ ((r & 7) << 4))),
                   g_A2 + (size_t)(n0 + r) * DD + chunk * 64 + g8 * 8);
    }
    #pragma unroll
    for (int u = 0; u < 4; u++) {
        int j = tid + u * 256;
        int r = j >> 3, g8 = j & 7;
        cp_async16(Ab + 16384u + (uint32_t)(r * 128 + ((g8 * 16) ^ ((r & 7) << 4))),
                   g_B2 + (size_t)(kb + r) * DD + chunk * 64 + g8 * 8);
    }
}

__global__ void __launch_bounds__(256, 2)
vq_mma_kernel() {
    extern __shared__ char smc[];
    const uint32_t sb = smem_u32(smc);
    float* wn_s = (float*)(smc + SM_WN);

    const int tid  = threadIdx.x;
    const int lane = tid & 31;
    const int warp = tid >> 5;
    const int wm   = warp >> 1;        // 0..3
    const int wnn  = warp & 1;         // 0..1
    const int n0   = blockIdx.x << 7;  // token base
    const int kb   = blockIdx.y << 7;  // code base

    if (tid < 128) wn_s[tid] = g_wnorm[kb + tid];

    issue_chunk(sb, 0, 0, n0, kb, tid); CP_COMMIT();
    issue_chunk(sb, 1, 1, n0, kb, tid); CP_COMMIT();

    float acc[2][8][4];
    #pragma unroll
    for (int i = 0; i < 2; i++)
        #pragma unroll
        for (int j = 0; j < 8; j++)
            #pragma unroll
            for (int e = 0; e < 4; e++) acc[i][j][e] = 0.0f;

    const int arow   = (lane & 7) | (((lane >> 3) & 1) << 3);
    const int akoffB = (lane >> 4) << 4;
    const int brow   = (lane & 7) | ((lane >> 4) << 3);
    const int bkoffB = ((lane >> 3) & 1) << 4;

    for (int c = 0; c < 4; c++) {
        if (c < 3) { CP_WAIT1(); } else { CP_WAIT0(); }
        __syncthreads();

        uint32_t Ab = sb + (uint32_t)(c & 1) * 32768u;
        uint32_t Bb = Ab + 16384u;

        #pragma unroll
        for (int k16 = 0; k16 < 4; k16++) {
            uint32_t a[2][4];
            #pragma unroll
            for (int mt = 0; mt < 2; mt++) {
                int r = wm * 32 + mt * 16 + arow;
                uint32_t ad = Ab + (uint32_t)(r * 128 +
                              ((k16 * 32 + akoffB) ^ ((r & 7) << 4)));
                LDSM_X4(a[mt][0], a[mt][1], a[mt][2], a[mt][3], ad);
            }
            uint32_t bf[8][2];
            #pragma unroll
            for (int p = 0; p < 4; p++) {
                int nl = wnn * 64 + p * 16 + brow;
                uint32_t bd = Bb + (uint32_t)(nl * 128 +
                              ((k16 * 32 + bkoffB) ^ ((nl & 7) << 4)));
                LDSM_X4(bf[2 * p][0], bf[2 * p][1], bf[2 * p + 1][0], bf[2 * p + 1][1], bd);
            }
            #pragma unroll
            for (int mt = 0; mt < 2; mt++)
                #pragma unroll
                for (int n8 = 0; n8 < 8; n8++)
                    MMA_BF16(acc[mt][n8], a[mt], bf[n8][0], bf[n8][1]);
        }
        __syncthreads();
        if (c < 2) { issue_chunk(sb, c & 1, c + 2, n0, kb, tid); CP_COMMIT(); }
    }

    // ---- epilogue: s = wn - 2*dot, fp16 pairs -> g_s ----
    const int g  = lane >> 2;
    const int qc = lane & 3;
    #pragma unroll
    for (int mt = 0; mt < 2; mt++) {
        #pragma unroll
        for (int h = 0; h < 2; h++) {
            int rl = wm * 32 + mt * 16 + h * 8 + g;
            uint32_t* rowp = (uint32_t*)(g_s + (size_t)(n0 + rl) * KK + kb + wnn * 64);
            #pragma unroll
            for (int n8 = 0; n8 < 8; n8++) {
                int cl0 = wnn * 64 + n8 * 8 + qc * 2;
                float s0 = __fmaf_rn(-2.0f, acc[mt][n8][h * 2 + 0], wn_s[cl0]);
                float s1 = __fmaf_rn(-2.0f, acc[mt][n8][h * 2 + 1], wn_s[cl0 + 1]);
                __half2 hp = __floats2half2_rn(s0, s1);
                rowp[n8 * 4 + qc] = *(uint32_t*)&hp;
            }
        }
    }
}

// ---------------------------------------------------------
// select: warp per token. Scan fp16 s row, candidates within EPS of min,
// exact fp32 recheck with the reference dist formula, first-index tie-break.
// Bound: bf16-gemm (2.3e-3) + fp16 store (3e-5) doubled + fp32 dist rounding
// (9e-5) < 4.8e-3; EPS = 1e-2 gives 2x margin.
#define EPS_SEL 1e-2f

__global__ void __launch_bounds__(256)
vq_select_kernel(const float* __restrict__ cb) {
    const int wid  = threadIdx.x >> 5;
    const int lane = threadIdx.x & 31;
    const int n    = blockIdx.x * 8 + wid;

    const uint4* srow = (const uint4*)(g_s + (size_t)n * KK);
    uint4 v[4];
    float m = 3.4e38f;
    #pragma unroll
    for (int j = 0; j < 4; j++) {
        v[j] = srow[lane + j * 32];
        const uint32_t* u = (const uint32_t*)&v[j];
        #pragma unroll
        for (int q = 0; q < 4; q++) {
            float2 f = __half22float2(*(const __half2*)&u[q]);
            m = fminf(m, fminf(f.x, f.y));
        }
    }
    #pragma unroll
    for (int o = 16; o; o >>= 1) m = fminf(m, __shfl_xor_sync(0xFFFFFFFFu, m, o));
    const float thresh = m + EPS_SEL;

    unsigned cmask = 0;
    #pragma unroll
    for (int j = 0; j < 4; j++) {
        const uint32_t* u = (const uint32_t*)&v[j];
        #pragma unroll
        for (int q = 0; q < 4; q++) {
            float2 f = __half22float2(*(const __half2*)&u[q]);
            if (f.x <= thresh) cmask |= 1u << (j * 8 + q * 2 + 0);
            if (f.y <= thresh) cmask |= 1u << (j * 8 + q * 2 + 1);
        }
    }

    const float xn = g_xnorm[n];
    const float4* xr = (const float4*)(g_Xt + (size_t)n * DD);
    float4 xa = xr[lane];
    float4 xb = xr[32 + lane];

    ull bestp = 0xFFFFFFFFFFFFFFFFULL;
    unsigned act;
    while ((act = __ballot_sync(0xFFFFFFFFu, cmask != 0)) != 0) {
        int leader = __ffs(act) - 1;
        int k = 0;
        if (lane == leader) {
            int bpos = __ffs(cmask) - 1;
            cmask &= cmask - 1;
            k = (lane + (bpos >> 3) * 32) * 8 + (bpos & 7);
        }
        k = __shfl_sync(0xFFFFFFFFu, k, leader);

        const float4* wr = (const float4*)(cb + (size_t)k * DD);
        float4 wa = wr[lane];
        float4 wb = wr[32 + lane];
        float s = 0.0f;
        s = __fmaf_rn(xa.x, wa.x, s); s = __fmaf_rn(xa.y, wa.y, s);
        s = __fmaf_rn(xa.z, wa.z, s); s = __fmaf_rn(xa.w, wa.w, s);
        s = __fmaf_rn(xb.x, wb.x, s); s = __fmaf_rn(xb.y, wb.y, s);
        s = __fmaf_rn(xb.z, wb.z, s); s = __fmaf_rn(xb.w, wb.w, s);
        #pragma unroll
        for (int o = 16; o; o >>= 1) s = __fadd_rn(s, __shfl_xor_sync(0xFFFFFFFFu, s, o));

        float dist = __fadd_rn(__fmaf_rn(-2.0f, s, xn), g_wnorm[k]);
        ull p = ((ull)__float_as_uint(dist) << 32) | (unsigned)k;
        if (p < bestp) bestp = p;
    }
    if (lane == 0) g_idx[n] = (unsigned)(bestp & 0xFFFFFFFFULL);
}

// ---------------------------------------------------------
// quantize + straight-through + loss + indices (coalesced along t)
__global__ void __launch_bounds__(256)
vq_quant_kernel(const float* __restrict__ lat, const float* __restrict__ cb,
                float* __restrict__ out) {
    extern __shared__ float qsm[];
    float*    q_s   = qsm;                             // [64][257]
    unsigned* idx_s = (unsigned*)(qsm + 64 * 257);     // [64]
    float*    red   = (float*)(idx_s + 64);            // [256]

    const int tid = threadIdx.x;
    const int cid = blockIdx.x;      // 0..511
    const int b   = cid >> 4;
    const int t0  = (cid & 15) << 6;

    if (tid < 64) {
        int n = b * TT + t0 + tid;
        unsigned k = g_idx[n];
        idx_s[tid] = k;
        out[OUT_IDX_OFF + n] = (float)k;
    }
    __syncthreads();

    {
        const float4* cb4 = (const float4*)cb;
        #pragma unroll
        for (int i = tid; i < 4096; i += 256) {
            int r = i >> 6, c4 = i & 63;
            float4 v = cb4[idx_s[r] * 64 + c4];
            float* q = q_s + r * 257 + c4 * 4;
            q[0] = v.x; q[1] = v.y; q[2] = v.z; q[3] = v.w;
        }
    }
    __syncthreads();

    const int tl = tid & 63;
    const int dg = tid >> 6;
    const int t  = t0 + tl;
    float lsum = 0.0f;
    #pragma unroll 8
    for (int dd = 0; dd < 64; dd++) {
        int d = dg * 64 + dd;
        size_t off = ((size_t)b * DD + d) * TT + t;
        float x = lat[off];
        float q = q_s[tl * 257 + d];
        float dq = __fsub_rn(q, x);
        out[OUT_Q_OFF + off] = __fadd_rn(x, dq);
        lsum = __fmaf_rn(dq, dq, lsum);
    }

    red[tid] = lsum;
    __syncthreads();
    for (int s = 128; s > 0; s >>= 1) {
        if (tid < s) red[tid] += red[tid + s];
        __syncthreads();
    }
    if (tid == 0) atomicAdd(&g_loss, (double)red[0]);
}

// ---------------------------------------------------------
__global__ void vq_finalize_kernel(float* __restrict__ out) {
    if (threadIdx.x == 0 && blockIdx.x == 0) {
        double mean = g_loss / (double)((size_t)NN * DD);
        out[OUT_LOSS_OFF] = (float)(mean * 1.25);
    }
}

// ---------------------------------------------------------
extern "C" void kernel_launch(void* const* d_in, const int* in_sizes, int n_in,
                              void* d_out, int out_size) {
    const float* lat = (const float*)d_in[0];   // [32, 256, 1024]
    const float* cb  = (const float*)d_in[1];   // [1024, 256]
    float* out = (float*)d_out;

    const int QUANT_SMEM = (64 * 257 + 64 + 256) * 4;   // 67072 B

    cudaFuncSetAttribute(vq_mma_kernel,
                         cudaFuncAttributeMaxDynamicSharedMemorySize, SM_TOTM);
    cudaFuncSetAttribute(vq_quant_kernel,
                         cudaFuncAttributeMaxDynamicSharedMemorySize, QUANT_SMEM);

    vq_prep_b_kernel<<<KK, 256>>>(cb);
    vq_prep_a_kernel<<<1024, 256>>>(lat);

    dim3 grid(256, 8);
    vq_mma_kernel<<<grid, 256, SM_TOTM>>>();

    vq_select_kernel<<<NN / 8, 256>>>(cb);
    vq_quant_kernel<<<512, 256, QUANT_SMEM>>>(lat, cb, out);
    vq_finalize_kernel<<<1, 1>>>(out);
}

// round 10
// speedup vs baseline: 4.1976x; 1.0920x over previous
#include <cuda_runtime.h>
#include <cuda_bf16.h>
#include <cuda_fp16.h>
#include <cstdint>

// Problem constants
#define BATCH 32
#define TT    1024
#define DD    256
#define KK    1024
#define NN    (BATCH*TT)
#define DT    (DD*TT)

#define OUT_Q_OFF    0
#define OUT_LOSS_OFF 8388608
#define OUT_IDX_OFF  8388609

typedef unsigned long long ull;

// -------- device scratch (no allocations allowed) --------
__device__ __half g_A2[(size_t)NN * DD];   // token-major fp16 latents
__device__ __half g_B2[(size_t)KK * DD];   // fp16 codebook
__device__ float  g_Xt[(size_t)NN * DD];   // token-major fp32 latents
__device__ __half g_s[(size_t)NN * KK];    // approx s = wn - 2*dot (fp16)
__device__ float  g_wnorm[KK];
__device__ float  g_xnorm[NN];
__device__ unsigned g_idx[NN];
__device__ double g_loss;

// -------- PTX helpers --------
__device__ __forceinline__ uint32_t smem_u32(const void* p) {
    uint32_t a;
    asm("{ .reg .u64 t; cvta.to.shared.u64 t, %1; cvt.u32.u64 %0, t; }"
        : "=r"(a) : "l"(p));
    return a;
}
__device__ __forceinline__ void cp_async16(uint32_t s, const void* g) {
    asm volatile("cp.async.cg.shared.global [%0], [%1], 16;" :: "r"(s), "l"(g));
}
#define CP_COMMIT() asm volatile("cp.async.commit_group;")
#define CP_WAIT1()  asm volatile("cp.async.wait_group 1;")
#define CP_WAIT0()  asm volatile("cp.async.wait_group 0;")

#define LDSM_X4(r0, r1, r2, r3, addr) \
    asm volatile("ldmatrix.sync.aligned.m8n8.x4.shared.b16 {%0,%1,%2,%3}, [%4];" \
        : "=r"(r0), "=r"(r1), "=r"(r2), "=r"(r3) : "r"(addr))

#define MMA_F16(c, a, b0, b1) \
    asm volatile("mma.sync.aligned.m16n8k16.row.col.f32.f16.f16.f32 " \
        "{%0,%1,%2,%3}, {%4,%5,%6,%7}, {%8,%9}, {%0,%1,%2,%3};" \
        : "+f"((c)[0]), "+f"((c)[1]), "+f"((c)[2]), "+f"((c)[3]) \
        : "r"((a)[0]), "r"((a)[1]), "r"((a)[2]), "r"((a)[3]), "r"(b0), "r"(b1))

// ---------------------------------------------------------
// prep B: fp16 codebook + wnorm; zero loss
__global__ void vq_prep_b_kernel(const float* __restrict__ cb) {
    __shared__ double sred[256];
    int k = blockIdx.x, d = threadIdx.x;
    float w = cb[k * DD + d];
    g_B2[(size_t)k * DD + d] = __float2half_rn(w);
    sred[d] = (double)w * (double)w;
    __syncthreads();
    for (int s = 128; s > 0; s >>= 1) {
        if (d < s) sred[d] += sred[d + s];
        __syncthreads();
    }
    if (d == 0) {
        g_wnorm[k] = (float)sred[0];
        if (k == 0) g_loss = 0.0;
    }
}

// prep A: transpose latents to token-major fp32 + fp16, fused xnorm (fp64).
__global__ void __launch_bounds__(256)
vq_prep_a_kernel(const float* __restrict__ lat) {
    __shared__ float  s[256 * 33];
    __shared__ double pr[256];
    const int tid = threadIdx.x;
    const int b   = blockIdx.x >> 5;
    const int t0  = (blockIdx.x & 31) << 5;

    #pragma unroll
    for (int i = tid; i < 2048; i += 256) {
        int d = i >> 3, tq = i & 7;
        float4 v = *(const float4*)(lat + ((size_t)b * DD + d) * TT + t0 + tq * 4);
        s[d * 33 + tq * 4 + 0] = v.x;
        s[d * 33 + tq * 4 + 1] = v.y;
        s[d * 33 + tq * 4 + 2] = v.z;
        s[d * 33 + tq * 4 + 3] = v.w;
    }
    __syncthreads();

    const int d = tid;
    #pragma unroll 4
    for (int tl = 0; tl < 32; tl++) {
        size_t n = (size_t)b * TT + t0 + tl;
        float x = s[d * 33 + tl];
        g_A2[n * DD + d] = __float2half_rn(x);
        g_Xt[n * DD + d] = x;
    }

    const int tk = tid & 31, dg = tid >> 5;
    double ssum = 0.0;
    #pragma unroll 8
    for (int dd = 0; dd < 32; dd++) {
        float v = s[(dg * 32 + dd) * 33 + tk];
        ssum += (double)v * (double)v;
    }
    pr[tid] = ssum;
    __syncthreads();
    if (tid < 32) {
        double tot = 0.0;
        #pragma unroll
        for (int j = 0; j < 8; j++) tot += pr[j * 32 + tid];
        g_xnorm[b * TT + t0 + tid] = (float)tot;
    }
}

// ---------------------------------------------------------
// main GEMM: CTA 128 tokens x 128 codes, K=256 in 4 chunks of 64,
// mma.sync m16n8k16 fp16, double-buffered cp.async tiles (SW128 swizzle).
// Epilogue writes fp16 surrogate s = wn - 2*dot.
#define SM_WN    65536
#define SM_TOTM  66048

__device__ __forceinline__ void issue_chunk(uint32_t sb, int bufsel, int chunk,
                                            int n0, int kb, int tid) {
    uint32_t Ab = sb + (uint32_t)bufsel * 32768u;
    #pragma unroll
    for (int u = 0; u < 4; u++) {
        int j = tid + u * 256;
        int r = j >> 3, g8 = j & 7;
        cp_async16(Ab + (uint32_t)(r * 128 + ((g8 * 16) ^ ((r & 7) << 4))),
                   g_A2 + (size_t)(n0 + r) * DD + chunk * 64 + g8 * 8);
    }
    #pragma unroll
    for (int u = 0; u < 4; u++) {
        int j = tid + u * 256;
        int r = j >> 3, g8 = j & 7;
        cp_async16(Ab + 16384u + (uint32_t)(r * 128 + ((g8 * 16) ^ ((r & 7) << 4))),
                   g_B2 + (size_t)(kb + r) * DD + chunk * 64 + g8 * 8);
    }
}

__global__ void __launch_bounds__(256, 2)
vq_mma_kernel() {
    extern __shared__ char smc[];
    const uint32_t sb = smem_u32(smc);
    float* wn_s = (float*)(smc + SM_WN);

    const int tid  = threadIdx.x;
    const int lane = tid & 31;
    const int warp = tid >> 5;
    const int wm   = warp >> 1;        // 0..3
    const int wnn  = warp & 1;         // 0..1
    const int n0   = blockIdx.x << 7;  // token base
    const int kb   = blockIdx.y << 7;  // code base

    if (tid < 128) wn_s[tid] = g_wnorm[kb + tid];

    issue_chunk(sb, 0, 0, n0, kb, tid); CP_COMMIT();
    issue_chunk(sb, 1, 1, n0, kb, tid); CP_COMMIT();

    float acc[2][8][4];
    #pragma unroll
    for (int i = 0; i < 2; i++)
        #pragma unroll
        for (int j = 0; j < 8; j++)
            #pragma unroll
            for (int e = 0; e < 4; e++) acc[i][j][e] = 0.0f;

    const int arow   = (lane & 7) | (((lane >> 3) & 1) << 3);
    const int akoffB = (lane >> 4) << 4;
    const int brow   = (lane & 7) | ((lane >> 4) << 3);
    const int bkoffB = ((lane >> 3) & 1) << 4;

    for (int c = 0; c < 4; c++) {
        if (c < 3) { CP_WAIT1(); } else { CP_WAIT0(); }
        __syncthreads();

        uint32_t Ab = sb + (uint32_t)(c & 1) * 32768u;
        uint32_t Bb = Ab + 16384u;

        #pragma unroll
        for (int k16 = 0; k16 < 4; k16++) {
            uint32_t a[2][4];
            #pragma unroll
            for (int mt = 0; mt < 2; mt++) {
                int r = wm * 32 + mt * 16 + arow;
                uint32_t ad = Ab + (uint32_t)(r * 128 +
                              ((k16 * 32 + akoffB) ^ ((r & 7) << 4)));
                LDSM_X4(a[mt][0], a[mt][1], a[mt][2], a[mt][3], ad);
            }
            uint32_t bf[8][2];
            #pragma unroll
            for (int p = 0; p < 4; p++) {
                int nl = wnn * 64 + p * 16 + brow;
                uint32_t bd = Bb + (uint32_t)(nl * 128 +
                              ((k16 * 32 + bkoffB) ^ ((nl & 7) << 4)));
                LDSM_X4(bf[2 * p][0], bf[2 * p][1], bf[2 * p + 1][0], bf[2 * p + 1][1], bd);
            }
            #pragma unroll
            for (int mt = 0; mt < 2; mt++)
                #pragma unroll
                for (int n8 = 0; n8 < 8; n8++)
                    MMA_F16(acc[mt][n8], a[mt], bf[n8][0], bf[n8][1]);
        }
        __syncthreads();
        if (c < 2) { issue_chunk(sb, c & 1, c + 2, n0, kb, tid); CP_COMMIT(); }
    }

    // ---- epilogue: s = wn - 2*dot, fp16 pairs -> g_s ----
    const int g  = lane >> 2;
    const int qc = lane & 3;
    #pragma unroll
    for (int mt = 0; mt < 2; mt++) {
        #pragma unroll
        for (int h = 0; h < 2; h++) {
            int rl = wm * 32 + mt * 16 + h * 8 + g;
            uint32_t* rowp = (uint32_t*)(g_s + (size_t)(n0 + rl) * KK + kb + wnn * 64);
            #pragma unroll
            for (int n8 = 0; n8 < 8; n8++) {
                int cl0 = wnn * 64 + n8 * 8 + qc * 2;
                float s0 = __fmaf_rn(-2.0f, acc[mt][n8][h * 2 + 0], wn_s[cl0]);
                float s1 = __fmaf_rn(-2.0f, acc[mt][n8][h * 2 + 1], wn_s[cl0 + 1]);
                __half2 hp = __floats2half2_rn(s0, s1);
                rowp[n8 * 4 + qc] = *(uint32_t*)&hp;
            }
        }
    }
}

// ---------------------------------------------------------
// select: warp per token. hmin2 scan of fp16 s row, chunk-prefiltered
// candidate mask, exact fp32 recheck with the reference dist formula,
// first-index tie-break.
// Bound: fp16-gemm (5.6e-4) + fp16 store (2.4e-4) per entry -> 2E ~ 1.6e-3;
// EPS = 4e-3 gives 2.5x margin.
#define EPS_SEL 4e-3f

__global__ void __launch_bounds__(256)
vq_select_kernel(const float* __restrict__ cb) {
    const int wid  = threadIdx.x >> 5;
    const int lane = threadIdx.x & 31;
    const int n    = blockIdx.x * 8 + wid;

    const uint4* srow = (const uint4*)(g_s + (size_t)n * KK);
    uint4 v[4];
    __half2 m2 = __floats2half2_rn(6.0e4f, 6.0e4f);
    #pragma unroll
    for (int j = 0; j < 4; j++) {
        v[j] = srow[lane + j * 32];
        const __half2* h = (const __half2*)&v[j];
        m2 = __hmin2(m2, __hmin2(__hmin2(h[0], h[1]), __hmin2(h[2], h[3])));
    }
    float m = fminf(__low2float(m2), __high2float(m2));
    #pragma unroll
    for (int o = 16; o; o >>= 1) m = fminf(m, __shfl_xor_sync(0xFFFFFFFFu, m, o));
    const float thresh = m + EPS_SEL;

    unsigned cmask = 0;
    #pragma unroll
    for (int j = 0; j < 4; j++) {
        const __half2* h = (const __half2*)&v[j];
        __half2 cm2 = __hmin2(__hmin2(h[0], h[1]), __hmin2(h[2], h[3]));
        float cmin = fminf(__low2float(cm2), __high2float(cm2));
        if (cmin <= thresh) {
            #pragma unroll
            for (int q = 0; q < 4; q++) {
                float2 f = __half22float2(h[q]);
                if (f.x <= thresh) cmask |= 1u << (j * 8 + q * 2 + 0);
                if (f.y <= thresh) cmask |= 1u << (j * 8 + q * 2 + 1);
            }
        }
    }

    const float xn = g_xnorm[n];
    const float4* xr = (const float4*)(g_Xt + (size_t)n * DD);
    float4 xa = xr[lane];
    float4 xb = xr[32 + lane];

    ull bestp = 0xFFFFFFFFFFFFFFFFULL;
    unsigned act;
    while ((act = __ballot_sync(0xFFFFFFFFu, cmask != 0)) != 0) {
        int leader = __ffs(act) - 1;
        int k = 0;
        if (lane == leader) {
            int bpos = __ffs(cmask) - 1;
            cmask &= cmask - 1;
            k = (lane + (bpos >> 3) * 32) * 8 + (bpos & 7);
        }
        k = __shfl_sync(0xFFFFFFFFu, k, leader);

        const float4* wr = (const float4*)(cb + (size_t)k * DD);
        float4 wa = wr[lane];
        float4 wb = wr[32 + lane];
        float s = 0.0f;
        s = __fmaf_rn(xa.x, wa.x, s); s = __fmaf_rn(xa.y, wa.y, s);
        s = __fmaf_rn(xa.z, wa.z, s); s = __fmaf_rn(xa.w, wa.w, s);
        s = __fmaf_rn(xb.x, wb.x, s); s = __fmaf_rn(xb.y, wb.y, s);
        s = __fmaf_rn(xb.z, wb.z, s); s = __fmaf_rn(xb.w, wb.w, s);
        #pragma unroll
        for (int o = 16; o; o >>= 1) s = __fadd_rn(s, __shfl_xor_sync(0xFFFFFFFFu, s, o));

        float dist = __fadd_rn(__fmaf_rn(-2.0f, s, xn), g_wnorm[k]);
        ull p = ((ull)__float_as_uint(dist) << 32) | (unsigned)k;
        if (p < bestp) bestp = p;
    }
    if (lane == 0) g_idx[n] = (unsigned)(bestp & 0xFFFFFFFFULL);
}

// ---------------------------------------------------------
// quantize + straight-through + loss + indices (coalesced along t)
__global__ void __launch_bounds__(256)
vq_quant_kernel(const float* __restrict__ lat, const float* __restrict__ cb,
                float* __restrict__ out) {
    extern __shared__ float qsm[];
    float*    q_s   = qsm;                             // [64][257]
    unsigned* idx_s = (unsigned*)(qsm + 64 * 257);     // [64]
    float*    red   = (float*)(idx_s + 64);            // [256]

    const int tid = threadIdx.x;
    const int cid = blockIdx.x;      // 0..511
    const int b   = cid >> 4;
    const int t0  = (cid & 15) << 6;

    if (tid < 64) {
        int n = b * TT + t0 + tid;
        unsigned k = g_idx[n];
        idx_s[tid] = k;
        out[OUT_IDX_OFF + n] = (float)k;
    }
    __syncthreads();

    {
        const float4* cb4 = (const float4*)cb;
        #pragma unroll
        for (int i = tid; i < 4096; i += 256) {
            int r = i >> 6, c4 = i & 63;
            float4 v = cb4[idx_s[r] * 64 + c4];
            float* q = q_s + r * 257 + c4 * 4;
            q[0] = v.x; q[1] = v.y; q[2] = v.z; q[3] = v.w;
        }
    }
    __syncthreads();

    const int tl = tid & 63;
    const int dg = tid >> 6;
    const int t  = t0 + tl;
    float lsum = 0.0f;
    #pragma unroll 8
    for (int dd = 0; dd < 64; dd++) {
        int d = dg * 64 + dd;
        size_t off = ((size_t)b * DD + d) * TT + t;
        float x = lat[off];
        float q = q_s[tl * 257 + d];
        float dq = __fsub_rn(q, x);
        out[OUT_Q_OFF + off] = __fadd_rn(x, dq);
        lsum = __fmaf_rn(dq, dq, lsum);
    }

    red[tid] = lsum;
    __syncthreads();
    for (int s = 128; s > 0; s >>= 1) {
        if (tid < s) red[tid] += red[tid + s];
        __syncthreads();
    }
    if (tid == 0) atomicAdd(&g_loss, (double)red[0]);
}

// ---------------------------------------------------------
__global__ void vq_finalize_kernel(float* __restrict__ out) {
    if (threadIdx.x == 0 && blockIdx.x == 0) {
        double mean = g_loss / (double)((size_t)NN * DD);
        out[OUT_LOSS_OFF] = (float)(mean * 1.25);
    }
}

// ---------------------------------------------------------
extern "C" void kernel_launch(void* const* d_in, const int* in_sizes, int n_in,
                              void* d_out, int out_size) {
    const float* lat = (const float*)d_in[0];   // [32, 256, 1024]
    const float* cb  = (const float*)d_in[1];   // [1024, 256]
    float* out = (float*)d_out;

    const int QUANT_SMEM = (64 * 257 + 64 + 256) * 4;   // 67072 B

    cudaFuncSetAttribute(vq_mma_kernel,
                         cudaFuncAttributeMaxDynamicSharedMemorySize, SM_TOTM);
    cudaFuncSetAttribute(vq_quant_kernel,
                         cudaFuncAttributeMaxDynamicSharedMemorySize, QUANT_SMEM);

    vq_prep_b_kernel<<<KK, 256>>>(cb);
    vq_prep_a_kernel<<<1024, 256>>>(lat);

    dim3 grid(256, 8);
    vq_mma_kernel<<<grid, 256, SM_TOTM>>>();

    vq_select_kernel<<<NN / 8, 256>>>(cb);
    vq_quant_kernel<<<512, 256, QUANT_SMEM>>>(lat, cb, out);
    vq_finalize_kernel<<<1, 1>>>(out);
}